// round 13
// baseline (speedup 1.0000x reference)
#include <cuda_runtime.h>
#include <cuda_bf16.h>
#include <cstdint>

// Problem constants
#define BB 2
#define SS 2048
#define DD 1024
#define HH 16
#define DEPTH 64
#define MROWS (BB * SS)          // 4096
#define QKV_N (3 * DD)           // 3072

#define N_X  (MROWS * DD)        // 4194304
#define N_WQ (DD * QKV_N)        // 3145728
#define N_WO (DD * DD)           // 1048576

// Scratch (allocation-free rule: __device__ globals), all bf16 hi/lo pairs
__device__ __nv_bfloat16 g_xh[N_X],  g_xl[N_X];
__device__ __nv_bfloat16 g_wqh[N_WQ], g_wql[N_WQ];
__device__ __nv_bfloat16 g_woh[N_WO], g_wol[N_WO];
__device__ __nv_bfloat16 g_qh[MROWS * QKV_N], g_ql[MROWS * QKV_N];
__device__ __nv_bfloat16 g_ah[N_X], g_al[N_X];

// ===========================================================================
// Helpers (base-target PTX: sm_80+, works on sm_103)
// ===========================================================================
__device__ __forceinline__ uint32_t smem_u32(const void* p) {
    uint32_t a;
    asm("{ .reg .u64 t; cvta.to.shared.u64 t, %1; cvt.u32.u64 %0, t; }"
        : "=r"(a) : "l"(p));
    return a;
}

__device__ __forceinline__ void ldsm_x4(uint32_t* r, uint32_t a) {
    asm volatile("ldmatrix.sync.aligned.m8n8.x4.shared.b16 {%0,%1,%2,%3}, [%4];"
                 : "=r"(r[0]), "=r"(r[1]), "=r"(r[2]), "=r"(r[3]) : "r"(a));
}

__device__ __forceinline__ void ldsm_x4_t(uint32_t* r, uint32_t a) {
    asm volatile("ldmatrix.sync.aligned.m8n8.x4.trans.shared.b16 {%0,%1,%2,%3}, [%4];"
                 : "=r"(r[0]), "=r"(r[1]), "=r"(r[2]), "=r"(r[3]) : "r"(a));
}

__device__ __forceinline__ void mma16816(float* c, const uint32_t* a,
                                         uint32_t b0, uint32_t b1) {
    asm volatile(
        "mma.sync.aligned.m16n8k16.row.col.f32.bf16.bf16.f32 "
        "{%0,%1,%2,%3}, {%4,%5,%6,%7}, {%8,%9}, {%0,%1,%2,%3};"
        : "+f"(c[0]), "+f"(c[1]), "+f"(c[2]), "+f"(c[3])
        : "r"(a[0]), "r"(a[1]), "r"(a[2]), "r"(a[3]), "r"(b0), "r"(b1));
}

__device__ __forceinline__ void cpa16(uint32_t d, const void* s) {
    asm volatile("cp.async.cg.shared.global [%0], [%1], 16;" :: "r"(d), "l"(s));
}
#define CP_COMMIT() asm volatile("cp.async.commit_group;" ::: "memory")
#define CP_WAIT2()  asm volatile("cp.async.wait_group 2;" ::: "memory")
#define CP_WAIT0()  asm volatile("cp.async.wait_group 0;" ::: "memory")

// Split fp32 -> (hi: truncated bf16, lo: rn bf16 of residual). Packs 2 at once.
__device__ __forceinline__ void split2(float x0, float x1,
                                       uint32_t& hi, uint32_t& lo) {
    uint32_t u0 = __float_as_uint(x0), u1 = __float_as_uint(x1);
    uint32_t h0 = u0 & 0xFFFF0000u,    h1 = u1 & 0xFFFF0000u;
    float l0 = x0 - __uint_as_float(h0);
    float l1 = x1 - __uint_as_float(h1);
    hi = (h0 >> 16) | h1;
    __nv_bfloat162 lp = __float22bfloat162_rn(make_float2(l0, l1));
    lo = *reinterpret_cast<uint32_t*>(&lp);
}

// ===========================================================================
// Prep: ONE kernel splitting x, W_qkv, W_out (fp32 -> bf16 hi/lo)
// ===========================================================================
__global__ void split3_kernel(const float* __restrict__ x,
                              const float* __restrict__ wq,
                              const float* __restrict__ wo,
                              __nv_bfloat16* __restrict__ xh, __nv_bfloat16* __restrict__ xl,
                              __nv_bfloat16* __restrict__ wqh, __nv_bfloat16* __restrict__ wql,
                              __nv_bfloat16* __restrict__ woh, __nv_bfloat16* __restrict__ wol)
{
    const int i = (blockIdx.x * blockDim.x + threadIdx.x) * 4;
    const float* src;
    __nv_bfloat16 *oh, *ol;
    int off;
    if (i < N_X)              { src = x;  oh = xh;  ol = xl;  off = i; }
    else if (i < N_X + N_WQ)  { src = wq; oh = wqh; ol = wql; off = i - N_X; }
    else                      { src = wo; oh = woh; ol = wol; off = i - N_X - N_WQ; }

    float4 v = *(const float4*)(src + off);
    uint32_t h0, l0, h1, l1;
    split2(v.x, v.y, h0, l0);
    split2(v.z, v.w, h1, l1);
    *(uint2*)(oh + off) = make_uint2(h0, h1);
    *(uint2*)(ol + off) = make_uint2(l0, l1);
}

// ===========================================================================
// bf16 hi/lo GEMM + bias. BM=64, BN=128, BK=32. 8 warps = 2(m) x 4(n),
// warp tile 32x32. cp.async 4-stage ring, wait_group 2 (THREE chunks in
// flight), one sync per chunk.
// Stage (27648 B): Ah 0 (64x80) | Al 5120 | Bh 10240 (32x272) | Bl 18944
// ===========================================================================
#define GSTAGE 27648
#define G_SMEM (4 * GSTAGE)

template<bool SPLIT_OUT>
__global__ __launch_bounds__(256, 2) void tgemm_bf16_kernel(
    const __nv_bfloat16* __restrict__ Ah, const __nv_bfloat16* __restrict__ Al,
    const __nv_bfloat16* __restrict__ Bh, const __nv_bfloat16* __restrict__ Bl,
    const float* __restrict__ bias,
    void* __restrict__ Cp, void* __restrict__ Clp,
    int N, int K)
{
    extern __shared__ char sm[];
    const uint32_t sb = smem_u32(sm);

    const int tid  = threadIdx.x;
    const int lane = tid & 31;
    const int wid  = tid >> 5;
    const int wm   = wid & 1;          // 0..1 -> rows wm*32
    const int wn   = wid >> 1;         // 0..3 -> cols wn*32

    const int rowBase = blockIdx.y * 64;
    const int colBase = blockIdx.x * 128;

    // loader mappings
    const int aRow = tid >> 2;             // 0..63
    const int aE0  = (tid & 3) * 8;        // 0,8,16,24 elems
    const int bK   = tid >> 3;             // 0..31
    const int bE0  = (tid & 7) * 16;       // 0..112 elems

    // ldmatrix bases (relative to stage start)
    const int laneM = lane & 15;
    const int laneH = lane >> 4;
    uint32_t aRel[2], bRel[2];
    #pragma unroll
    for (int i = 0; i < 2; ++i)
        aRel[i] = (uint32_t)(wm * 32 + i * 16 + laneM) * 80 + laneH * 16;
    #pragma unroll
    for (int j = 0; j < 2; ++j)
        bRel[j] = 10240u + (uint32_t)laneM * 272
                + (uint32_t)(wn * 32 + j * 16 + laneH * 8) * 2;

    float acc[2][4][4];
    #pragma unroll
    for (int i = 0; i < 2; ++i)
        #pragma unroll
        for (int n = 0; n < 4; ++n)
            #pragma unroll
            for (int c = 0; c < 4; ++c) acc[i][n][c] = 0.f;

    const int nChunks = K >> 5;

    auto issue = [&](int ck) {
        const uint32_t st = sb + (uint32_t)(ck & 3) * GSTAGE;
        const int k0 = ck << 5;
        {   // A rows: 4 threads/row, 8 elems (16B) each
            const size_t gi = (size_t)(rowBase + aRow) * K + k0 + aE0;
            const uint32_t d = st + (uint32_t)aRow * 80 + aE0 * 2;
            cpa16(d,        Ah + gi);
            cpa16(d + 5120, Al + gi);
        }
        {   // B rows [k][n]: 8 threads/row, 16 elems (2x16B) each
            const size_t gi = (size_t)(k0 + bK) * N + colBase + bE0;
            const uint32_t d = st + 10240u + (uint32_t)bK * 272 + bE0 * 2;
            cpa16(d,             Bh + gi);
            cpa16(d + 16,        Bh + gi + 8);
            cpa16(d + 8704,      Bl + gi);
            cpa16(d + 8704 + 16, Bl + gi + 8);
        }
    };

    issue(0); CP_COMMIT();
    issue(1); CP_COMMIT();
    issue(2); CP_COMMIT();

    for (int ck = 0; ck < nChunks; ++ck) {
        CP_WAIT2();          // chunk ck complete (ck+1, ck+2 may be in flight)
        __syncthreads();     // visibility + everyone done with chunk ck-1
        if (ck + 3 < nChunks) issue(ck + 3);   // stage consumed at ck-1 -> free
        CP_COMMIT();

        const uint32_t st = sb + (uint32_t)(ck & 3) * GSTAGE;
        #pragma unroll
        for (int ks = 0; ks < 2; ++ks) {
            const uint32_t aOff = st + ks * 32;
            const uint32_t bOff = st + ks * 16 * 272;
            uint32_t ah[2][4], al[2][4], bh[2][4], bl[2][4];
            #pragma unroll
            for (int i = 0; i < 2; ++i) {
                ldsm_x4(ah[i], aRel[i] + aOff);
                ldsm_x4(al[i], aRel[i] + aOff + 5120);
            }
            #pragma unroll
            for (int j = 0; j < 2; ++j) {
                ldsm_x4_t(bh[j], bRel[j] + bOff);
                ldsm_x4_t(bl[j], bRel[j] + bOff + 8704);
            }
            #pragma unroll
            for (int i = 0; i < 2; ++i) {
                #pragma unroll
                for (int n = 0; n < 4; ++n) {
                    const int j = n >> 1, h = (n & 1) * 2;
                    mma16816(acc[i][n], ah[i], bh[j][h], bh[j][h + 1]);
                    mma16816(acc[i][n], ah[i], bl[j][h], bl[j][h + 1]);
                    mma16816(acc[i][n], al[i], bh[j][h], bh[j][h + 1]);
                }
            }
        }
    }
    CP_WAIT0();

    // ---- epilogue ----------------------------------------------------------
    #pragma unroll
    for (int i = 0; i < 2; ++i) {
        const int r0 = rowBase + wm * 32 + i * 16 + (lane >> 2);
        #pragma unroll
        for (int n = 0; n < 4; ++n) {
            const int c = colBase + wn * 32 + n * 8 + (lane & 3) * 2;
            const float b0 = bias[c], b1 = bias[c + 1];
            const float v00 = acc[i][n][0] + b0, v01 = acc[i][n][1] + b1;
            const float v10 = acc[i][n][2] + b0, v11 = acc[i][n][3] + b1;
            if (SPLIT_OUT) {
                __nv_bfloat16* Ch = (__nv_bfloat16*)Cp;
                __nv_bfloat16* Cl = (__nv_bfloat16*)Clp;
                uint32_t hi, lo;
                split2(v00, v01, hi, lo);
                *(uint32_t*)&Ch[(size_t)r0 * N + c] = hi;
                *(uint32_t*)&Cl[(size_t)r0 * N + c] = lo;
                split2(v10, v11, hi, lo);
                *(uint32_t*)&Ch[(size_t)(r0 + 8) * N + c] = hi;
                *(uint32_t*)&Cl[(size_t)(r0 + 8) * N + c] = lo;
            } else {
                float* Cc = (float*)Cp;
                *(float2*)&Cc[(size_t)r0 * N + c]       = make_float2(v00, v01);
                *(float2*)&Cc[(size_t)(r0 + 8) * N + c] = make_float2(v10, v11);
            }
        }
    }
}

// ===========================================================================
// Tensor-core causal flash attention (R10 passing version, unchanged).
// 1D grid with GLOBAL LPT order; exp2-domain softmax.
// ===========================================================================
#define ASTR 144
#define FQ_LO 18432
#define FKV0 36864
#define KVSTG 36864
#define FATTN_SMEM 110592
#define NQT (SS / 128)        // 16 q tiles
#define NBH (BB * HH)         // 32 heads

__global__ __launch_bounds__(256, 2) void fattn_kernel(
    const __nv_bfloat16* __restrict__ qkvh,
    const __nv_bfloat16* __restrict__ qkvl,
    __nv_bfloat16* __restrict__ outh,
    __nv_bfloat16* __restrict__ outl)
{
    extern __shared__ char sm[];
    const uint32_t sb = smem_u32(sm);

    const int tid  = threadIdx.x;
    const int lane = tid & 31;
    const int w    = tid >> 5;
    const int g    = lane >> 2;
    const int t2   = (lane & 3) * 2;

    const int qt = (NQT - 1) - (int)(blockIdx.x >> 5);
    const int bh = blockIdx.x & (NBH - 1);
    const int b  = bh >> 4;
    const int h  = bh & 15;
    const int qbase = qt * 128;

    const int kvR  = tid >> 2;
    const int kvC0 = (tid & 3) * 16;
    auto issueKV = [&](int kt) {
        const uint32_t st = sb + FKV0 + (uint32_t)(kt & 1) * KVSTG;
        const size_t gi = (size_t)(b * SS + kt * 64 + kvR) * QKV_N + h * 192 + 64 + kvC0;
        const uint32_t d = st + (uint32_t)kvR * ASTR + kvC0 * 2;
        cpa16(d,              qkvh + gi);
        cpa16(d + 16,         qkvh + gi + 8);
        cpa16(d + 9216,       qkvl + gi);
        cpa16(d + 9216 + 16,  qkvl + gi + 8);
        cpa16(d + 18432,      qkvh + gi + 64);
        cpa16(d + 18432 + 16, qkvh + gi + 72);
        cpa16(d + 27648,      qkvl + gi + 64);
        cpa16(d + 27648 + 16, qkvl + gi + 72);
    };

    {
        const int qrow = tid >> 1;
        const int qc0  = (tid & 1) * 32;
        const size_t gi = (size_t)(b * SS + qbase + qrow) * QKV_N + h * 192 + qc0;
        char* dh = sm + qrow * ASTR + qc0 * 2;
        char* dl = sm + FQ_LO + qrow * ASTR + qc0 * 2;
        #pragma unroll
        for (int j = 0; j < 4; ++j) {
            *(uint4*)(dh + j * 16) = *(const uint4*)(qkvh + gi + j * 8);
            *(uint4*)(dl + j * 16) = *(const uint4*)(qkvl + gi + j * 8);
        }
    }
    issueKV(0); CP_COMMIT();
    __syncthreads();

    uint32_t qh[4][4], ql[4][4];
    {
        const uint32_t qa = sb + (uint32_t)(w * 16 + (lane & 15)) * ASTR + (lane >> 4) * 16;
        #pragma unroll
        for (int ks = 0; ks < 4; ++ks) {
            ldsm_x4(qh[ks], qa + ks * 32);
            ldsm_x4(ql[ks], qa + FQ_LO + ks * 32);
        }
    }

    float O[8][4];
    #pragma unroll
    for (int n = 0; n < 8; ++n)
        #pragma unroll
        for (int c = 0; c < 4; ++c) O[n][c] = 0.f;
    float m0 = -1e30f, m1 = -1e30f, l0 = 0.f, l1 = 0.f;

    const uint32_t kRel = (uint32_t)((lane & 7) + ((lane >> 4) & 1) * 8) * ASTR
                        + ((lane >> 3) & 1) * 16;
    const uint32_t vRel = (uint32_t)(lane & 15) * ASTR + (uint32_t)(lane >> 4) * 16;

    const int rowbase = qbase + w * 16;
    const int ktMax = qbase / 64 + 1;
    const float SCL = 0.125f * 1.4426950408889634f;

    for (int kt = 0; kt <= ktMax; ++kt) {
        const int kvbase = kt * 64;
        CP_WAIT0();
        __syncthreads();
        if (kt + 1 <= ktMax) issueKV(kt + 1);
        CP_COMMIT();

        if (kvbase > rowbase + 15) continue;

        const uint32_t stK = sb + FKV0 + (uint32_t)(kt & 1) * KVSTG;
        const uint32_t stV = stK + 18432;

        float S[8][4];
        #pragma unroll
        for (int n = 0; n < 8; ++n)
            #pragma unroll
            for (int c = 0; c < 4; ++c) S[n][c] = 0.f;

        #pragma unroll
        for (int ks = 0; ks < 4; ++ks) {
            uint32_t kb[4][4], kl_[4][4];
            #pragma unroll
            for (int j = 0; j < 4; ++j) {
                const uint32_t ka = stK + kRel + (uint32_t)j * 16 * ASTR + ks * 32;
                ldsm_x4(kb[j],  ka);
                ldsm_x4(kl_[j], ka + 9216);
            }
            #pragma unroll
            for (int n = 0; n < 8; ++n) {
                const int j = n >> 1, hh = (n & 1) * 2;
                mma16816(S[n], qh[ks], kb[j][hh],  kb[j][hh + 1]);
                mma16816(S[n], qh[ks], kl_[j][hh], kl_[j][hh + 1]);
                mma16816(S[n], ql[ks], kb[j][hh],  kb[j][hh + 1]);
            }
        }

        #pragma unroll
        for (int n = 0; n < 8; ++n) {
            S[n][0] *= SCL; S[n][1] *= SCL;
            S[n][2] *= SCL; S[n][3] *= SCL;
        }
        if (kvbase + 63 > rowbase) {
            #pragma unroll
            for (int n = 0; n < 8; ++n) {
                const int colb = kvbase + n * 8 + t2;
                if (colb > rowbase + g)          S[n][0] = -1e30f;
                if (colb + 1 > rowbase + g)      S[n][1] = -1e30f;
                if (colb > rowbase + g + 8)      S[n][2] = -1e30f;
                if (colb + 1 > rowbase + g + 8)  S[n][3] = -1e30f;
            }
        }

        float tm0 = -1e30f, tm1 = -1e30f;
        #pragma unroll
        for (int n = 0; n < 8; ++n) {
            tm0 = fmaxf(tm0, fmaxf(S[n][0], S[n][1]));
            tm1 = fmaxf(tm1, fmaxf(S[n][2], S[n][3]));
        }
        tm0 = fmaxf(tm0, __shfl_xor_sync(0xFFFFFFFFu, tm0, 1));
        tm0 = fmaxf(tm0, __shfl_xor_sync(0xFFFFFFFFu, tm0, 2));
        tm1 = fmaxf(tm1, __shfl_xor_sync(0xFFFFFFFFu, tm1, 1));
        tm1 = fmaxf(tm1, __shfl_xor_sync(0xFFFFFFFFu, tm1, 2));

        const float mn0 = fmaxf(m0, tm0);
        const float mn1 = fmaxf(m1, tm1);
        const float cr0 = exp2f(m0 - mn0);
        const float cr1 = exp2f(m1 - mn1);
        l0 *= cr0; l1 *= cr1;
        #pragma unroll
        for (int n = 0; n < 8; ++n) {
            O[n][0] *= cr0; O[n][1] *= cr0;
            O[n][2] *= cr1; O[n][3] *= cr1;
        }
        #pragma unroll
        for (int n = 0; n < 8; ++n) {
            S[n][0] = exp2f(S[n][0] - mn0);
            S[n][1] = exp2f(S[n][1] - mn0);
            S[n][2] = exp2f(S[n][2] - mn1);
            S[n][3] = exp2f(S[n][3] - mn1);
            l0 += S[n][0] + S[n][1];
            l1 += S[n][2] + S[n][3];
        }
        m0 = mn0; m1 = mn1;

        uint32_t ph[4][4], pl[4][4];
        #pragma unroll
        for (int j = 0; j < 4; ++j) {
            split2(S[2 * j][0],     S[2 * j][1],     ph[j][0], pl[j][0]);
            split2(S[2 * j][2],     S[2 * j][3],     ph[j][1], pl[j][1]);
            split2(S[2 * j + 1][0], S[2 * j + 1][1], ph[j][2], pl[j][2]);
            split2(S[2 * j + 1][2], S[2 * j + 1][3], ph[j][3], pl[j][3]);
        }

        #pragma unroll
        for (int ks = 0; ks < 4; ++ks) {
            uint32_t vb[4][4], vl_[4][4];
            #pragma unroll
            for (int j = 0; j < 4; ++j) {
                const uint32_t va = stV + vRel + (uint32_t)ks * 16 * ASTR + (uint32_t)j * 32;
                ldsm_x4_t(vb[j],  va);
                ldsm_x4_t(vl_[j], va + 9216);
            }
            #pragma unroll
            for (int n = 0; n < 8; ++n) {
                const int j = n >> 1, hh = (n & 1) * 2;
                mma16816(O[n], ph[ks], vb[j][hh],  vb[j][hh + 1]);
                mma16816(O[n], ph[ks], vl_[j][hh], vl_[j][hh + 1]);
                mma16816(O[n], pl[ks], vb[j][hh],  vb[j][hh + 1]);
            }
        }
    }
    CP_WAIT0();

    l0 += __shfl_xor_sync(0xFFFFFFFFu, l0, 1);
    l0 += __shfl_xor_sync(0xFFFFFFFFu, l0, 2);
    l1 += __shfl_xor_sync(0xFFFFFFFFu, l1, 1);
    l1 += __shfl_xor_sync(0xFFFFFFFFu, l1, 2);
    const float inv0 = 1.f / l0;
    const float inv1 = 1.f / l1;

    const size_t row0 = (size_t)(b * SS + rowbase + g);
    #pragma unroll
    for (int n = 0; n < 8; ++n) {
        const int c = h * DEPTH + n * 8 + t2;
        uint32_t hi, lo;
        split2(O[n][0] * inv0, O[n][1] * inv0, hi, lo);
        *(uint32_t*)&outh[row0 * DD + c] = hi;
        *(uint32_t*)&outl[row0 * DD + c] = lo;
        split2(O[n][2] * inv1, O[n][3] * inv1, hi, lo);
        *(uint32_t*)&outh[(row0 + 8) * DD + c] = hi;
        *(uint32_t*)&outl[(row0 + 8) * DD + c] = lo;
    }
}

// ---------------------------------------------------------------------------
// Launch: 1 merged split prep -> QKV GEMM(split out) -> flash attn
//         -> out GEMM(f32 out).
// ---------------------------------------------------------------------------
extern "C" void kernel_launch(void* const* d_in, const int* in_sizes, int n_in,
                              void* d_out, int out_size)
{
    const float* x     = (const float*)d_in[0];
    const float* Wqkv  = (const float*)d_in[2];
    const float* bqkv  = (const float*)d_in[3];
    const float* Wout  = (const float*)d_in[4];
    const float* bout  = (const float*)d_in[5];
    float* out = (float*)d_out;

    __nv_bfloat16 *xh, *xl, *wqh, *wql, *woh, *wol, *qh, *ql, *ah, *al;
    { void* p; cudaGetSymbolAddress(&p, g_xh);  xh  = (__nv_bfloat16*)p; }
    { void* p; cudaGetSymbolAddress(&p, g_xl);  xl  = (__nv_bfloat16*)p; }
    { void* p; cudaGetSymbolAddress(&p, g_wqh); wqh = (__nv_bfloat16*)p; }
    { void* p; cudaGetSymbolAddress(&p, g_wql); wql = (__nv_bfloat16*)p; }
    { void* p; cudaGetSymbolAddress(&p, g_woh); woh = (__nv_bfloat16*)p; }
    { void* p; cudaGetSymbolAddress(&p, g_wol); wol = (__nv_bfloat16*)p; }
    { void* p; cudaGetSymbolAddress(&p, g_qh);  qh  = (__nv_bfloat16*)p; }
    { void* p; cudaGetSymbolAddress(&p, g_ql);  ql  = (__nv_bfloat16*)p; }
    { void* p; cudaGetSymbolAddress(&p, g_ah);  ah  = (__nv_bfloat16*)p; }
    { void* p; cudaGetSymbolAddress(&p, g_al);  al  = (__nv_bfloat16*)p; }

    static bool attr_set = false;
    if (!attr_set) {
        cudaFuncSetAttribute(tgemm_bf16_kernel<true>,
                             cudaFuncAttributeMaxDynamicSharedMemorySize, G_SMEM);
        cudaFuncSetAttribute(tgemm_bf16_kernel<false>,
                             cudaFuncAttributeMaxDynamicSharedMemorySize, G_SMEM);
        cudaFuncSetAttribute(fattn_kernel,
                             cudaFuncAttributeMaxDynamicSharedMemorySize, FATTN_SMEM);
        attr_set = true;
    }

    // 0) merged pre-split of x, W_qkv, W_out (exact multiple: no bounds check)
    split3_kernel<<<(N_X + N_WQ + N_WO) / 4 / 256, 256>>>(
        x, Wqkv, Wout, xh, xl, wqh, wql, woh, wol);

    // 1) QKV projection -> split bf16 qkv
    {
        dim3 grid(QKV_N / 128, MROWS / 64);
        tgemm_bf16_kernel<true><<<grid, 256, G_SMEM>>>(
            xh, xl, wqh, wql, bqkv, qh, ql, QKV_N, DD);
    }
    // 2) causal flash attention -> split bf16 attn (1D LPT grid)
    {
        fattn_kernel<<<NQT * NBH, 256, FATTN_SMEM>>>(qh, ql, ah, al);
    }
    // 3) output projection -> fp32 out
    {
        dim3 grid(DD / 128, MROWS / 64);
        tgemm_bf16_kernel<false><<<grid, 256, G_SMEM>>>(
            ah, al, woh, wol, bout, out, nullptr, DD, DD);
    }
}

// round 14
// speedup vs baseline: 1.0145x; 1.0145x over previous
#include <cuda_runtime.h>
#include <cuda_bf16.h>
#include <cstdint>

// Problem constants
#define BB 2
#define SS 2048
#define DD 1024
#define HH 16
#define DEPTH 64
#define MROWS (BB * SS)          // 4096
#define QKV_N (3 * DD)           // 3072

#define N_X  (MROWS * DD)        // 4194304
#define N_WQ (DD * QKV_N)        // 3145728
#define N_WO (DD * DD)           // 1048576

// Scratch (allocation-free rule: __device__ globals), all bf16 hi/lo pairs
__device__ __nv_bfloat16 g_xh[N_X],  g_xl[N_X];
__device__ __nv_bfloat16 g_wqh[N_WQ], g_wql[N_WQ];
__device__ __nv_bfloat16 g_woh[N_WO], g_wol[N_WO];
__device__ __nv_bfloat16 g_qh[MROWS * QKV_N], g_ql[MROWS * QKV_N];
__device__ __nv_bfloat16 g_ah[N_X], g_al[N_X];

// ===========================================================================
// Helpers (base-target PTX: sm_80+, works on sm_103)
// ===========================================================================
__device__ __forceinline__ uint32_t smem_u32(const void* p) {
    uint32_t a;
    asm("{ .reg .u64 t; cvta.to.shared.u64 t, %1; cvt.u32.u64 %0, t; }"
        : "=r"(a) : "l"(p));
    return a;
}

__device__ __forceinline__ void ldsm_x4(uint32_t* r, uint32_t a) {
    asm volatile("ldmatrix.sync.aligned.m8n8.x4.shared.b16 {%0,%1,%2,%3}, [%4];"
                 : "=r"(r[0]), "=r"(r[1]), "=r"(r[2]), "=r"(r[3]) : "r"(a));
}

__device__ __forceinline__ void ldsm_x4_t(uint32_t* r, uint32_t a) {
    asm volatile("ldmatrix.sync.aligned.m8n8.x4.trans.shared.b16 {%0,%1,%2,%3}, [%4];"
                 : "=r"(r[0]), "=r"(r[1]), "=r"(r[2]), "=r"(r[3]) : "r"(a));
}

__device__ __forceinline__ void mma16816(float* c, const uint32_t* a,
                                         uint32_t b0, uint32_t b1) {
    asm volatile(
        "mma.sync.aligned.m16n8k16.row.col.f32.bf16.bf16.f32 "
        "{%0,%1,%2,%3}, {%4,%5,%6,%7}, {%8,%9}, {%0,%1,%2,%3};"
        : "+f"(c[0]), "+f"(c[1]), "+f"(c[2]), "+f"(c[3])
        : "r"(a[0]), "r"(a[1]), "r"(a[2]), "r"(a[3]), "r"(b0), "r"(b1));
}

__device__ __forceinline__ void cpa16(uint32_t d, const void* s) {
    asm volatile("cp.async.cg.shared.global [%0], [%1], 16;" :: "r"(d), "l"(s));
}
#define CP_COMMIT() asm volatile("cp.async.commit_group;" ::: "memory")
#define CP_WAIT1()  asm volatile("cp.async.wait_group 1;" ::: "memory")
#define CP_WAIT0()  asm volatile("cp.async.wait_group 0;" ::: "memory")

// Split fp32 -> (hi: truncated bf16, lo: rn bf16 of residual). Packs 2 at once.
__device__ __forceinline__ void split2(float x0, float x1,
                                       uint32_t& hi, uint32_t& lo) {
    uint32_t u0 = __float_as_uint(x0), u1 = __float_as_uint(x1);
    uint32_t h0 = u0 & 0xFFFF0000u,    h1 = u1 & 0xFFFF0000u;
    float l0 = x0 - __uint_as_float(h0);
    float l1 = x1 - __uint_as_float(h1);
    hi = (h0 >> 16) | h1;
    __nv_bfloat162 lp = __float22bfloat162_rn(make_float2(l0, l1));
    lo = *reinterpret_cast<uint32_t*>(&lp);
}

// ===========================================================================
// Prep: ONE kernel splitting x, W_qkv, W_out (fp32 -> bf16 hi/lo)
// ===========================================================================
__global__ void split3_kernel(const float* __restrict__ x,
                              const float* __restrict__ wq,
                              const float* __restrict__ wo,
                              __nv_bfloat16* __restrict__ xh, __nv_bfloat16* __restrict__ xl,
                              __nv_bfloat16* __restrict__ wqh, __nv_bfloat16* __restrict__ wql,
                              __nv_bfloat16* __restrict__ woh, __nv_bfloat16* __restrict__ wol)
{
    const int i = (blockIdx.x * blockDim.x + threadIdx.x) * 4;
    const float* src;
    __nv_bfloat16 *oh, *ol;
    int off;
    if (i < N_X)              { src = x;  oh = xh;  ol = xl;  off = i; }
    else if (i < N_X + N_WQ)  { src = wq; oh = wqh; ol = wql; off = i - N_X; }
    else                      { src = wo; oh = woh; ol = wol; off = i - N_X - N_WQ; }

    float4 v = *(const float4*)(src + off);
    uint32_t h0, l0, h1, l1;
    split2(v.x, v.y, h0, l0);
    split2(v.z, v.w, h1, l1);
    *(uint2*)(oh + off) = make_uint2(h0, h1);
    *(uint2*)(ol + off) = make_uint2(l0, l1);
}

// ===========================================================================
// bf16 hi/lo GEMM + bias (R12 proven config).
// BM=64, BN=128, BK=32. 8 warps = 2(m) x 4(n), warp tile 32x32.
// cp.async 3-stage ring, wait_group 1 (two chunks in flight), one sync/chunk.
// Stage (27648 B): Ah 0 (64x80) | Al 5120 | Bh 10240 (32x272) | Bl 18944
// ===========================================================================
#define GSTAGE 27648
#define G_SMEM (3 * GSTAGE)

template<bool SPLIT_OUT>
__global__ __launch_bounds__(256, 2) void tgemm_bf16_kernel(
    const __nv_bfloat16* __restrict__ Ah, const __nv_bfloat16* __restrict__ Al,
    const __nv_bfloat16* __restrict__ Bh, const __nv_bfloat16* __restrict__ Bl,
    const float* __restrict__ bias,
    void* __restrict__ Cp, void* __restrict__ Clp,
    int N, int K)
{
    extern __shared__ char sm[];
    const uint32_t sb = smem_u32(sm);

    const int tid  = threadIdx.x;
    const int lane = tid & 31;
    const int wid  = tid >> 5;
    const int wm   = wid & 1;          // 0..1 -> rows wm*32
    const int wn   = wid >> 1;         // 0..3 -> cols wn*32

    const int rowBase = blockIdx.y * 64;
    const int colBase = blockIdx.x * 128;

    // loader mappings
    const int aRow = tid >> 2;             // 0..63
    const int aE0  = (tid & 3) * 8;        // 0,8,16,24 elems
    const int bK   = tid >> 3;             // 0..31
    const int bE0  = (tid & 7) * 16;       // 0..112 elems

    // ldmatrix bases (relative to stage start)
    const int laneM = lane & 15;
    const int laneH = lane >> 4;
    uint32_t aRel[2], bRel[2];
    #pragma unroll
    for (int i = 0; i < 2; ++i)
        aRel[i] = (uint32_t)(wm * 32 + i * 16 + laneM) * 80 + laneH * 16;
    #pragma unroll
    for (int j = 0; j < 2; ++j)
        bRel[j] = 10240u + (uint32_t)laneM * 272
                + (uint32_t)(wn * 32 + j * 16 + laneH * 8) * 2;

    float acc[2][4][4];
    #pragma unroll
    for (int i = 0; i < 2; ++i)
        #pragma unroll
        for (int n = 0; n < 4; ++n)
            #pragma unroll
            for (int c = 0; c < 4; ++c) acc[i][n][c] = 0.f;

    const int nChunks = K >> 5;

    auto issue = [&](int ck, uint32_t stOff) {
        const uint32_t st = sb + stOff;
        const int k0 = ck << 5;
        {   // A rows: 4 threads/row, 8 elems (16B) each
            const size_t gi = (size_t)(rowBase + aRow) * K + k0 + aE0;
            const uint32_t d = st + (uint32_t)aRow * 80 + aE0 * 2;
            cpa16(d,        Ah + gi);
            cpa16(d + 5120, Al + gi);
        }
        {   // B rows [k][n]: 8 threads/row, 16 elems (2x16B) each
            const size_t gi = (size_t)(k0 + bK) * N + colBase + bE0;
            const uint32_t d = st + 10240u + (uint32_t)bK * 272 + bE0 * 2;
            cpa16(d,             Bh + gi);
            cpa16(d + 16,        Bh + gi + 8);
            cpa16(d + 8704,      Bl + gi);
            cpa16(d + 8704 + 16, Bl + gi + 8);
        }
    };

    issue(0, 0); CP_COMMIT();
    issue(1, GSTAGE); CP_COMMIT();

    uint32_t stOff = 0;
    for (int ck = 0; ck < nChunks; ++ck) {
        CP_WAIT1();          // chunk ck complete (ck+1 may be in flight)
        __syncthreads();     // visibility + everyone done with chunk ck-1
        if (ck + 2 < nChunks) {
            uint32_t issOff = stOff + 2 * GSTAGE;
            if (issOff >= 3 * GSTAGE) issOff -= 3 * GSTAGE;
            issue(ck + 2, issOff);
        }
        CP_COMMIT();

        const uint32_t st = sb + stOff;
        #pragma unroll
        for (int ks = 0; ks < 2; ++ks) {
            const uint32_t aOff = st + ks * 32;
            const uint32_t bOff = st + ks * 16 * 272;
            uint32_t ah[2][4], al[2][4], bh[2][4], bl[2][4];
            #pragma unroll
            for (int i = 0; i < 2; ++i) {
                ldsm_x4(ah[i], aRel[i] + aOff);
                ldsm_x4(al[i], aRel[i] + aOff + 5120);
            }
            #pragma unroll
            for (int j = 0; j < 2; ++j) {
                ldsm_x4_t(bh[j], bRel[j] + bOff);
                ldsm_x4_t(bl[j], bRel[j] + bOff + 8704);
            }
            #pragma unroll
            for (int i = 0; i < 2; ++i) {
                #pragma unroll
                for (int n = 0; n < 4; ++n) {
                    const int j = n >> 1, h = (n & 1) * 2;
                    mma16816(acc[i][n], ah[i], bh[j][h], bh[j][h + 1]);
                    mma16816(acc[i][n], ah[i], bl[j][h], bl[j][h + 1]);
                    mma16816(acc[i][n], al[i], bh[j][h], bh[j][h + 1]);
                }
            }
        }
        stOff += GSTAGE;
        if (stOff >= 3 * GSTAGE) stOff = 0;
    }
    CP_WAIT0();

    // ---- epilogue ----------------------------------------------------------
    #pragma unroll
    for (int i = 0; i < 2; ++i) {
        const int r0 = rowBase + wm * 32 + i * 16 + (lane >> 2);
        #pragma unroll
        for (int n = 0; n < 4; ++n) {
            const int c = colBase + wn * 32 + n * 8 + (lane & 3) * 2;
            const float b0 = bias[c], b1 = bias[c + 1];
            const float v00 = acc[i][n][0] + b0, v01 = acc[i][n][1] + b1;
            const float v10 = acc[i][n][2] + b0, v11 = acc[i][n][3] + b1;
            if (SPLIT_OUT) {
                __nv_bfloat16* Ch = (__nv_bfloat16*)Cp;
                __nv_bfloat16* Cl = (__nv_bfloat16*)Clp;
                uint32_t hi, lo;
                split2(v00, v01, hi, lo);
                *(uint32_t*)&Ch[(size_t)r0 * N + c] = hi;
                *(uint32_t*)&Cl[(size_t)r0 * N + c] = lo;
                split2(v10, v11, hi, lo);
                *(uint32_t*)&Ch[(size_t)(r0 + 8) * N + c] = hi;
                *(uint32_t*)&Cl[(size_t)(r0 + 8) * N + c] = lo;
            } else {
                float* Cc = (float*)Cp;
                *(float2*)&Cc[(size_t)r0 * N + c]       = make_float2(v00, v01);
                *(float2*)&Cc[(size_t)(r0 + 8) * N + c] = make_float2(v10, v11);
            }
        }
    }
}

// ===========================================================================
// Tensor-core causal flash attention, bf16 hi/lo I/O.
// 1D grid with GLOBAL LPT order; exp2-domain softmax.
// kv loop reordered: sync -> issue(kt+1) -> wait_group 1 -> compute(kt)
// (next tile's cp.async issues before this warp blocks on tile kt).
// smem: Q_hi 0, Q_lo 18432; KV stage s at 36864 + s*36864. Total 110592.
// ===========================================================================
#define ASTR 144
#define FQ_LO 18432
#define FKV0 36864
#define KVSTG 36864
#define FATTN_SMEM 110592
#define NQT (SS / 128)        // 16 q tiles
#define NBH (BB * HH)         // 32 heads

__global__ __launch_bounds__(256, 2) void fattn_kernel(
    const __nv_bfloat16* __restrict__ qkvh,
    const __nv_bfloat16* __restrict__ qkvl,
    __nv_bfloat16* __restrict__ outh,
    __nv_bfloat16* __restrict__ outl)
{
    extern __shared__ char sm[];
    const uint32_t sb = smem_u32(sm);

    const int tid  = threadIdx.x;
    const int lane = tid & 31;
    const int w    = tid >> 5;
    const int g    = lane >> 2;
    const int t2   = (lane & 3) * 2;

    const int qt = (NQT - 1) - (int)(blockIdx.x >> 5);
    const int bh = blockIdx.x & (NBH - 1);
    const int b  = bh >> 4;
    const int h  = bh & 15;
    const int qbase = qt * 128;

    const int kvR  = tid >> 2;
    const int kvC0 = (tid & 3) * 16;
    auto issueKV = [&](int kt) {
        const uint32_t st = sb + FKV0 + (uint32_t)(kt & 1) * KVSTG;
        const size_t gi = (size_t)(b * SS + kt * 64 + kvR) * QKV_N + h * 192 + 64 + kvC0;
        const uint32_t d = st + (uint32_t)kvR * ASTR + kvC0 * 2;
        cpa16(d,              qkvh + gi);
        cpa16(d + 16,         qkvh + gi + 8);
        cpa16(d + 9216,       qkvl + gi);
        cpa16(d + 9216 + 16,  qkvl + gi + 8);
        cpa16(d + 18432,      qkvh + gi + 64);
        cpa16(d + 18432 + 16, qkvh + gi + 72);
        cpa16(d + 27648,      qkvl + gi + 64);
        cpa16(d + 27648 + 16, qkvl + gi + 72);
    };

    // ---- stage Q (plain stores) + kick off kv tile 0 -------------------------
    {
        const int qrow = tid >> 1;
        const int qc0  = (tid & 1) * 32;
        const size_t gi = (size_t)(b * SS + qbase + qrow) * QKV_N + h * 192 + qc0;
        char* dh = sm + qrow * ASTR + qc0 * 2;
        char* dl = sm + FQ_LO + qrow * ASTR + qc0 * 2;
        #pragma unroll
        for (int j = 0; j < 4; ++j) {
            *(uint4*)(dh + j * 16) = *(const uint4*)(qkvh + gi + j * 8);
            *(uint4*)(dl + j * 16) = *(const uint4*)(qkvl + gi + j * 8);
        }
    }
    issueKV(0); CP_COMMIT();
    __syncthreads();

    // ---- Q fragments in registers for whole kv loop --------------------------
    uint32_t qh[4][4], ql[4][4];
    {
        const uint32_t qa = sb + (uint32_t)(w * 16 + (lane & 15)) * ASTR + (lane >> 4) * 16;
        #pragma unroll
        for (int ks = 0; ks < 4; ++ks) {
            ldsm_x4(qh[ks], qa + ks * 32);
            ldsm_x4(ql[ks], qa + FQ_LO + ks * 32);
        }
    }

    float O[8][4];
    #pragma unroll
    for (int n = 0; n < 8; ++n)
        #pragma unroll
        for (int c = 0; c < 4; ++c) O[n][c] = 0.f;
    float m0 = -1e30f, m1 = -1e30f, l0 = 0.f, l1 = 0.f;

    const uint32_t kRel = (uint32_t)((lane & 7) + ((lane >> 4) & 1) * 8) * ASTR
                        + ((lane >> 3) & 1) * 16;
    const uint32_t vRel = (uint32_t)(lane & 15) * ASTR + (uint32_t)(lane >> 4) * 16;

    const int rowbase = qbase + w * 16;
    const int ktMax = qbase / 64 + 1;
    const float SCL = 0.125f * 1.4426950408889634f;

    for (int kt = 0; kt <= ktMax; ++kt) {
        const int kvbase = kt * 64;
        __syncthreads();                       // all warps done with tile kt-1
        if (kt + 1 <= ktMax) issueKV(kt + 1);  // buffer consumed at kt-1 -> free
        CP_COMMIT();
        CP_WAIT1();                            // tile kt landed (kt+1 in flight)

        if (kvbase > rowbase + 15) continue;   // warp tile fully masked

        const uint32_t stK = sb + FKV0 + (uint32_t)(kt & 1) * KVSTG;
        const uint32_t stV = stK + 18432;

        // ---- S = Q K^T -------------------------------------------------------
        float S[8][4];
        #pragma unroll
        for (int n = 0; n < 8; ++n)
            #pragma unroll
            for (int c = 0; c < 4; ++c) S[n][c] = 0.f;

        #pragma unroll
        for (int ks = 0; ks < 4; ++ks) {
            uint32_t kb[4][4], kl_[4][4];
            #pragma unroll
            for (int j = 0; j < 4; ++j) {
                const uint32_t ka = stK + kRel + (uint32_t)j * 16 * ASTR + ks * 32;
                ldsm_x4(kb[j],  ka);
                ldsm_x4(kl_[j], ka + 9216);
            }
            #pragma unroll
            for (int n = 0; n < 8; ++n) {
                const int j = n >> 1, hh = (n & 1) * 2;
                mma16816(S[n], qh[ks], kb[j][hh],  kb[j][hh + 1]);
                mma16816(S[n], qh[ks], kl_[j][hh], kl_[j][hh + 1]);
                mma16816(S[n], ql[ks], kb[j][hh],  kb[j][hh + 1]);
            }
        }

        // scale into exp2 domain + causal mask
        #pragma unroll
        for (int n = 0; n < 8; ++n) {
            S[n][0] *= SCL; S[n][1] *= SCL;
            S[n][2] *= SCL; S[n][3] *= SCL;
        }
        if (kvbase + 63 > rowbase) {
            #pragma unroll
            for (int n = 0; n < 8; ++n) {
                const int colb = kvbase + n * 8 + t2;
                if (colb > rowbase + g)          S[n][0] = -1e30f;
                if (colb + 1 > rowbase + g)      S[n][1] = -1e30f;
                if (colb > rowbase + g + 8)      S[n][2] = -1e30f;
                if (colb + 1 > rowbase + g + 8)  S[n][3] = -1e30f;
            }
        }

        // ---- online softmax (exp2 domain) --------------------------------------
        float tm0 = -1e30f, tm1 = -1e30f;
        #pragma unroll
        for (int n = 0; n < 8; ++n) {
            tm0 = fmaxf(tm0, fmaxf(S[n][0], S[n][1]));
            tm1 = fmaxf(tm1, fmaxf(S[n][2], S[n][3]));
        }
        tm0 = fmaxf(tm0, __shfl_xor_sync(0xFFFFFFFFu, tm0, 1));
        tm0 = fmaxf(tm0, __shfl_xor_sync(0xFFFFFFFFu, tm0, 2));
        tm1 = fmaxf(tm1, __shfl_xor_sync(0xFFFFFFFFu, tm1, 1));
        tm1 = fmaxf(tm1, __shfl_xor_sync(0xFFFFFFFFu, tm1, 2));

        const float mn0 = fmaxf(m0, tm0);
        const float mn1 = fmaxf(m1, tm1);
        const float cr0 = exp2f(m0 - mn0);
        const float cr1 = exp2f(m1 - mn1);
        l0 *= cr0; l1 *= cr1;
        #pragma unroll
        for (int n = 0; n < 8; ++n) {
            O[n][0] *= cr0; O[n][1] *= cr0;
            O[n][2] *= cr1; O[n][3] *= cr1;
        }
        #pragma unroll
        for (int n = 0; n < 8; ++n) {
            S[n][0] = exp2f(S[n][0] - mn0);
            S[n][1] = exp2f(S[n][1] - mn0);
            S[n][2] = exp2f(S[n][2] - mn1);
            S[n][3] = exp2f(S[n][3] - mn1);
            l0 += S[n][0] + S[n][1];
            l1 += S[n][2] + S[n][3];
        }
        m0 = mn0; m1 = mn1;

        // ---- pack P fragments (hi/lo) -----------------------------------------
        uint32_t ph[4][4], pl[4][4];
        #pragma unroll
        for (int j = 0; j < 4; ++j) {
            split2(S[2 * j][0],     S[2 * j][1],     ph[j][0], pl[j][0]);
            split2(S[2 * j][2],     S[2 * j][3],     ph[j][1], pl[j][1]);
            split2(S[2 * j + 1][0], S[2 * j + 1][1], ph[j][2], pl[j][2]);
            split2(S[2 * j + 1][2], S[2 * j + 1][3], ph[j][3], pl[j][3]);
        }

        // ---- O += P V -----------------------------------------------------------
        #pragma unroll
        for (int ks = 0; ks < 4; ++ks) {
            uint32_t vb[4][4], vl_[4][4];
            #pragma unroll
            for (int j = 0; j < 4; ++j) {
                const uint32_t va = stV + vRel + (uint32_t)ks * 16 * ASTR + (uint32_t)j * 32;
                ldsm_x4_t(vb[j],  va);
                ldsm_x4_t(vl_[j], va + 9216);
            }
            #pragma unroll
            for (int n = 0; n < 8; ++n) {
                const int j = n >> 1, hh = (n & 1) * 2;
                mma16816(O[n], ph[ks], vb[j][hh],  vb[j][hh + 1]);
                mma16816(O[n], ph[ks], vl_[j][hh], vl_[j][hh + 1]);
                mma16816(O[n], pl[ks], vb[j][hh],  vb[j][hh + 1]);
            }
        }
    }
    CP_WAIT0();

    // ---- finalize: reduce l, scale, split-store ------------------------------
    l0 += __shfl_xor_sync(0xFFFFFFFFu, l0, 1);
    l0 += __shfl_xor_sync(0xFFFFFFFFu, l0, 2);
    l1 += __shfl_xor_sync(0xFFFFFFFFu, l1, 1);
    l1 += __shfl_xor_sync(0xFFFFFFFFu, l1, 2);
    const float inv0 = 1.f / l0;
    const float inv1 = 1.f / l1;

    const size_t row0 = (size_t)(b * SS + rowbase + g);
    #pragma unroll
    for (int n = 0; n < 8; ++n) {
        const int c = h * DEPTH + n * 8 + t2;
        uint32_t hi, lo;
        split2(O[n][0] * inv0, O[n][1] * inv0, hi, lo);
        *(uint32_t*)&outh[row0 * DD + c] = hi;
        *(uint32_t*)&outl[row0 * DD + c] = lo;
        split2(O[n][2] * inv1, O[n][3] * inv1, hi, lo);
        *(uint32_t*)&outh[(row0 + 8) * DD + c] = hi;
        *(uint32_t*)&outl[(row0 + 8) * DD + c] = lo;
    }
}

// ---------------------------------------------------------------------------
// Launch: 1 merged split prep -> QKV GEMM(split out) -> flash attn
//         -> out GEMM(f32 out).
// ---------------------------------------------------------------------------
extern "C" void kernel_launch(void* const* d_in, const int* in_sizes, int n_in,
                              void* d_out, int out_size)
{
    const float* x     = (const float*)d_in[0];
    const float* Wqkv  = (const float*)d_in[2];
    const float* bqkv  = (const float*)d_in[3];
    const float* Wout  = (const float*)d_in[4];
    const float* bout  = (const float*)d_in[5];
    float* out = (float*)d_out;

    __nv_bfloat16 *xh, *xl, *wqh, *wql, *woh, *wol, *qh, *ql, *ah, *al;
    { void* p; cudaGetSymbolAddress(&p, g_xh);  xh  = (__nv_bfloat16*)p; }
    { void* p; cudaGetSymbolAddress(&p, g_xl);  xl  = (__nv_bfloat16*)p; }
    { void* p; cudaGetSymbolAddress(&p, g_wqh); wqh = (__nv_bfloat16*)p; }
    { void* p; cudaGetSymbolAddress(&p, g_wql); wql = (__nv_bfloat16*)p; }
    { void* p; cudaGetSymbolAddress(&p, g_woh); woh = (__nv_bfloat16*)p; }
    { void* p; cudaGetSymbolAddress(&p, g_wol); wol = (__nv_bfloat16*)p; }
    { void* p; cudaGetSymbolAddress(&p, g_qh);  qh  = (__nv_bfloat16*)p; }
    { void* p; cudaGetSymbolAddress(&p, g_ql);  ql  = (__nv_bfloat16*)p; }
    { void* p; cudaGetSymbolAddress(&p, g_ah);  ah  = (__nv_bfloat16*)p; }
    { void* p; cudaGetSymbolAddress(&p, g_al);  al  = (__nv_bfloat16*)p; }

    static bool attr_set = false;
    if (!attr_set) {
        cudaFuncSetAttribute(tgemm_bf16_kernel<true>,
                             cudaFuncAttributeMaxDynamicSharedMemorySize, G_SMEM);
        cudaFuncSetAttribute(tgemm_bf16_kernel<false>,
                             cudaFuncAttributeMaxDynamicSharedMemorySize, G_SMEM);
        cudaFuncSetAttribute(fattn_kernel,
                             cudaFuncAttributeMaxDynamicSharedMemorySize, FATTN_SMEM);
        attr_set = true;
    }

    // 0) merged pre-split of x, W_qkv, W_out (exact multiple: no bounds check)
    split3_kernel<<<(N_X + N_WQ + N_WO) / 4 / 256, 256>>>(
        x, Wqkv, Wout, xh, xl, wqh, wql, woh, wol);

    // 1) QKV projection -> split bf16 qkv
    {
        dim3 grid(QKV_N / 128, MROWS / 64);
        tgemm_bf16_kernel<true><<<grid, 256, G_SMEM>>>(
            xh, xl, wqh, wql, bqkv, qh, ql, QKV_N, DD);
    }
    // 2) causal flash attention -> split bf16 attn (1D LPT grid)
    {
        fattn_kernel<<<NQT * NBH, 256, FATTN_SMEM>>>(qh, ql, ah, al);
    }
    // 3) output projection -> fp32 out
    {
        dim3 grid(DD / 128, MROWS / 64);
        tgemm_bf16_kernel<false><<<grid, 256, G_SMEM>>>(
            ah, al, woh, wol, bout, out, nullptr, DD, DD);
    }
}

// round 15
// speedup vs baseline: 1.0318x; 1.0170x over previous
#include <cuda_runtime.h>
#include <cuda_bf16.h>
#include <cstdint>

// Problem constants
#define BB 2
#define SS 2048
#define DD 1024
#define HH 16
#define DEPTH 64
#define MROWS (BB * SS)          // 4096
#define QKV_N (3 * DD)           // 3072

#define N_X  (MROWS * DD)        // 4194304
#define N_WQ (DD * QKV_N)        // 3145728
#define N_WO (DD * DD)           // 1048576

// Scratch (allocation-free rule: __device__ globals), all bf16 hi/lo pairs
__device__ __nv_bfloat16 g_xh[N_X],  g_xl[N_X];
__device__ __nv_bfloat16 g_wqh[N_WQ], g_wql[N_WQ];
__device__ __nv_bfloat16 g_woh[N_WO], g_wol[N_WO];
__device__ __nv_bfloat16 g_qh[MROWS * QKV_N], g_ql[MROWS * QKV_N];
__device__ __nv_bfloat16 g_ah[N_X], g_al[N_X];

// ===========================================================================
// Helpers (base-target PTX: sm_80+, works on sm_103)
// ===========================================================================
__device__ __forceinline__ uint32_t smem_u32(const void* p) {
    uint32_t a;
    asm("{ .reg .u64 t; cvta.to.shared.u64 t, %1; cvt.u32.u64 %0, t; }"
        : "=r"(a) : "l"(p));
    return a;
}

__device__ __forceinline__ void ldsm_x4(uint32_t* r, uint32_t a) {
    asm volatile("ldmatrix.sync.aligned.m8n8.x4.shared.b16 {%0,%1,%2,%3}, [%4];"
                 : "=r"(r[0]), "=r"(r[1]), "=r"(r[2]), "=r"(r[3]) : "r"(a));
}

__device__ __forceinline__ void ldsm_x4_t(uint32_t* r, uint32_t a) {
    asm volatile("ldmatrix.sync.aligned.m8n8.x4.trans.shared.b16 {%0,%1,%2,%3}, [%4];"
                 : "=r"(r[0]), "=r"(r[1]), "=r"(r[2]), "=r"(r[3]) : "r"(a));
}

__device__ __forceinline__ void mma16816(float* c, const uint32_t* a,
                                         uint32_t b0, uint32_t b1) {
    asm volatile(
        "mma.sync.aligned.m16n8k16.row.col.f32.bf16.bf16.f32 "
        "{%0,%1,%2,%3}, {%4,%5,%6,%7}, {%8,%9}, {%0,%1,%2,%3};"
        : "+f"(c[0]), "+f"(c[1]), "+f"(c[2]), "+f"(c[3])
        : "r"(a[0]), "r"(a[1]), "r"(a[2]), "r"(a[3]), "r"(b0), "r"(b1));
}

__device__ __forceinline__ void cpa16(uint32_t d, const void* s) {
    asm volatile("cp.async.cg.shared.global [%0], [%1], 16;" :: "r"(d), "l"(s));
}
#define CP_COMMIT() asm volatile("cp.async.commit_group;" ::: "memory")
#define CP_WAIT1()  asm volatile("cp.async.wait_group 1;" ::: "memory")
#define CP_WAIT0()  asm volatile("cp.async.wait_group 0;" ::: "memory")

// Split fp32 -> (hi: truncated bf16, lo: rn bf16 of residual). Packs 2 at once.
__device__ __forceinline__ void split2(float x0, float x1,
                                       uint32_t& hi, uint32_t& lo) {
    uint32_t u0 = __float_as_uint(x0), u1 = __float_as_uint(x1);
    uint32_t h0 = u0 & 0xFFFF0000u,    h1 = u1 & 0xFFFF0000u;
    float l0 = x0 - __uint_as_float(h0);
    float l1 = x1 - __uint_as_float(h1);
    hi = (h0 >> 16) | h1;
    __nv_bfloat162 lp = __float22bfloat162_rn(make_float2(l0, l1));
    lo = *reinterpret_cast<uint32_t*>(&lp);
}

// ===========================================================================
// Prep: ONE kernel splitting x, W_qkv, W_out (fp32 -> bf16 hi/lo)
// ===========================================================================
__global__ void split3_kernel(const float* __restrict__ x,
                              const float* __restrict__ wq,
                              const float* __restrict__ wo,
                              __nv_bfloat16* __restrict__ xh, __nv_bfloat16* __restrict__ xl,
                              __nv_bfloat16* __restrict__ wqh, __nv_bfloat16* __restrict__ wql,
                              __nv_bfloat16* __restrict__ woh, __nv_bfloat16* __restrict__ wol)
{
    const int i = (blockIdx.x * blockDim.x + threadIdx.x) * 4;
    const float* src;
    __nv_bfloat16 *oh, *ol;
    int off;
    if (i < N_X)              { src = x;  oh = xh;  ol = xl;  off = i; }
    else if (i < N_X + N_WQ)  { src = wq; oh = wqh; ol = wql; off = i - N_X; }
    else                      { src = wo; oh = woh; ol = wol; off = i - N_X - N_WQ; }

    float4 v = *(const float4*)(src + off);
    uint32_t h0, l0, h1, l1;
    split2(v.x, v.y, h0, l0);
    split2(v.z, v.w, h1, l1);
    *(uint2*)(oh + off) = make_uint2(h0, h1);
    *(uint2*)(ol + off) = make_uint2(l0, l1);
}

// ===========================================================================
// bf16 hi/lo GEMM + bias. BM=64, BN=128, BK=32. 8 warps = 2(m) x 4(n),
// warp tile 32x32. OCCUPANCY-3 EXPERIMENT: 2-stage ring, wait_group 0,
// 3 CTAs/SM (smem 2x27648 = 55296; x3 = 166KB; regs capped by bounds).
// Pipeline: wait0(ck landed) -> sync -> issue(ck+1, other buffer) -> compute.
// Stage (27648 B): Ah 0 (64x80) | Al 5120 | Bh 10240 (32x272) | Bl 18944
// ===========================================================================
#define GSTAGE 27648
#define G_SMEM (2 * GSTAGE)

template<bool SPLIT_OUT>
__global__ __launch_bounds__(256, 3) void tgemm_bf16_kernel(
    const __nv_bfloat16* __restrict__ Ah, const __nv_bfloat16* __restrict__ Al,
    const __nv_bfloat16* __restrict__ Bh, const __nv_bfloat16* __restrict__ Bl,
    const float* __restrict__ bias,
    void* __restrict__ Cp, void* __restrict__ Clp,
    int N, int K)
{
    extern __shared__ char sm[];
    const uint32_t sb = smem_u32(sm);

    const int tid  = threadIdx.x;
    const int lane = tid & 31;
    const int wid  = tid >> 5;
    const int wm   = wid & 1;          // 0..1 -> rows wm*32
    const int wn   = wid >> 1;         // 0..3 -> cols wn*32

    const int rowBase = blockIdx.y * 64;
    const int colBase = blockIdx.x * 128;

    // loader mappings
    const int aRow = tid >> 2;             // 0..63
    const int aE0  = (tid & 3) * 8;        // 0,8,16,24 elems
    const int bK   = tid >> 3;             // 0..31
    const int bE0  = (tid & 7) * 16;       // 0..112 elems

    // ldmatrix bases (relative to stage start)
    const int laneM = lane & 15;
    const int laneH = lane >> 4;
    uint32_t aRel[2], bRel[2];
    #pragma unroll
    for (int i = 0; i < 2; ++i)
        aRel[i] = (uint32_t)(wm * 32 + i * 16 + laneM) * 80 + laneH * 16;
    #pragma unroll
    for (int j = 0; j < 2; ++j)
        bRel[j] = 10240u + (uint32_t)laneM * 272
                + (uint32_t)(wn * 32 + j * 16 + laneH * 8) * 2;

    float acc[2][4][4];
    #pragma unroll
    for (int i = 0; i < 2; ++i)
        #pragma unroll
        for (int n = 0; n < 4; ++n)
            #pragma unroll
            for (int c = 0; c < 4; ++c) acc[i][n][c] = 0.f;

    const int nChunks = K >> 5;

    auto issue = [&](int ck) {
        const uint32_t st = sb + (uint32_t)(ck & 1) * GSTAGE;
        const int k0 = ck << 5;
        {   // A rows: 4 threads/row, 8 elems (16B) each
            const size_t gi = (size_t)(rowBase + aRow) * K + k0 + aE0;
            const uint32_t d = st + (uint32_t)aRow * 80 + aE0 * 2;
            cpa16(d,        Ah + gi);
            cpa16(d + 5120, Al + gi);
        }
        {   // B rows [k][n]: 8 threads/row, 16 elems (2x16B) each
            const size_t gi = (size_t)(k0 + bK) * N + colBase + bE0;
            const uint32_t d = st + 10240u + (uint32_t)bK * 272 + bE0 * 2;
            cpa16(d,             Bh + gi);
            cpa16(d + 16,        Bh + gi + 8);
            cpa16(d + 8704,      Bl + gi);
            cpa16(d + 8704 + 16, Bl + gi + 8);
        }
    };

    issue(0); CP_COMMIT();

    for (int ck = 0; ck < nChunks; ++ck) {
        CP_WAIT0();          // chunk ck landed (only group outstanding)
        __syncthreads();     // visibility + everyone done with chunk ck-1
        if (ck + 1 < nChunks) issue(ck + 1);   // other buffer, freed at ck-1
        CP_COMMIT();

        const uint32_t st = sb + (uint32_t)(ck & 1) * GSTAGE;
        #pragma unroll
        for (int ks = 0; ks < 2; ++ks) {
            const uint32_t aOff = st + ks * 32;
            const uint32_t bOff = st + ks * 16 * 272;
            uint32_t ah[2][4], al[2][4], bh[2][4], bl[2][4];
            #pragma unroll
            for (int i = 0; i < 2; ++i) {
                ldsm_x4(ah[i], aRel[i] + aOff);
                ldsm_x4(al[i], aRel[i] + aOff + 5120);
            }
            #pragma unroll
            for (int j = 0; j < 2; ++j) {
                ldsm_x4_t(bh[j], bRel[j] + bOff);
                ldsm_x4_t(bl[j], bRel[j] + bOff + 8704);
            }
            #pragma unroll
            for (int i = 0; i < 2; ++i) {
                #pragma unroll
                for (int n = 0; n < 4; ++n) {
                    const int j = n >> 1, h = (n & 1) * 2;
                    mma16816(acc[i][n], ah[i], bh[j][h], bh[j][h + 1]);
                    mma16816(acc[i][n], ah[i], bl[j][h], bl[j][h + 1]);
                    mma16816(acc[i][n], al[i], bh[j][h], bh[j][h + 1]);
                }
            }
        }
    }
    CP_WAIT0();

    // ---- epilogue ----------------------------------------------------------
    #pragma unroll
    for (int i = 0; i < 2; ++i) {
        const int r0 = rowBase + wm * 32 + i * 16 + (lane >> 2);
        #pragma unroll
        for (int n = 0; n < 4; ++n) {
            const int c = colBase + wn * 32 + n * 8 + (lane & 3) * 2;
            const float b0 = bias[c], b1 = bias[c + 1];
            const float v00 = acc[i][n][0] + b0, v01 = acc[i][n][1] + b1;
            const float v10 = acc[i][n][2] + b0, v11 = acc[i][n][3] + b1;
            if (SPLIT_OUT) {
                __nv_bfloat16* Ch = (__nv_bfloat16*)Cp;
                __nv_bfloat16* Cl = (__nv_bfloat16*)Clp;
                uint32_t hi, lo;
                split2(v00, v01, hi, lo);
                *(uint32_t*)&Ch[(size_t)r0 * N + c] = hi;
                *(uint32_t*)&Cl[(size_t)r0 * N + c] = lo;
                split2(v10, v11, hi, lo);
                *(uint32_t*)&Ch[(size_t)(r0 + 8) * N + c] = hi;
                *(uint32_t*)&Cl[(size_t)(r0 + 8) * N + c] = lo;
            } else {
                float* Cc = (float*)Cp;
                *(float2*)&Cc[(size_t)r0 * N + c]       = make_float2(v00, v01);
                *(float2*)&Cc[(size_t)(r0 + 8) * N + c] = make_float2(v10, v11);
            }
        }
    }
}

// ===========================================================================
// Tensor-core causal flash attention (R14 passing version, unchanged).
// 1D grid with GLOBAL LPT order; exp2-domain softmax.
// kv loop: sync -> issue(kt+1) -> wait_group 1 -> compute(kt).
// smem: Q_hi 0, Q_lo 18432; KV stage s at 36864 + s*36864. Total 110592.
// ===========================================================================
#define ASTR 144
#define FQ_LO 18432
#define FKV0 36864
#define KVSTG 36864
#define FATTN_SMEM 110592
#define NQT (SS / 128)        // 16 q tiles
#define NBH (BB * HH)         // 32 heads

__global__ __launch_bounds__(256, 2) void fattn_kernel(
    const __nv_bfloat16* __restrict__ qkvh,
    const __nv_bfloat16* __restrict__ qkvl,
    __nv_bfloat16* __restrict__ outh,
    __nv_bfloat16* __restrict__ outl)
{
    extern __shared__ char sm[];
    const uint32_t sb = smem_u32(sm);

    const int tid  = threadIdx.x;
    const int lane = tid & 31;
    const int w    = tid >> 5;
    const int g    = lane >> 2;
    const int t2   = (lane & 3) * 2;

    const int qt = (NQT - 1) - (int)(blockIdx.x >> 5);
    const int bh = blockIdx.x & (NBH - 1);
    const int b  = bh >> 4;
    const int h  = bh & 15;
    const int qbase = qt * 128;

    const int kvR  = tid >> 2;
    const int kvC0 = (tid & 3) * 16;
    auto issueKV = [&](int kt) {
        const uint32_t st = sb + FKV0 + (uint32_t)(kt & 1) * KVSTG;
        const size_t gi = (size_t)(b * SS + kt * 64 + kvR) * QKV_N + h * 192 + 64 + kvC0;
        const uint32_t d = st + (uint32_t)kvR * ASTR + kvC0 * 2;
        cpa16(d,              qkvh + gi);
        cpa16(d + 16,         qkvh + gi + 8);
        cpa16(d + 9216,       qkvl + gi);
        cpa16(d + 9216 + 16,  qkvl + gi + 8);
        cpa16(d + 18432,      qkvh + gi + 64);
        cpa16(d + 18432 + 16, qkvh + gi + 72);
        cpa16(d + 27648,      qkvl + gi + 64);
        cpa16(d + 27648 + 16, qkvl + gi + 72);
    };

    {
        const int qrow = tid >> 1;
        const int qc0  = (tid & 1) * 32;
        const size_t gi = (size_t)(b * SS + qbase + qrow) * QKV_N + h * 192 + qc0;
        char* dh = sm + qrow * ASTR + qc0 * 2;
        char* dl = sm + FQ_LO + qrow * ASTR + qc0 * 2;
        #pragma unroll
        for (int j = 0; j < 4; ++j) {
            *(uint4*)(dh + j * 16) = *(const uint4*)(qkvh + gi + j * 8);
            *(uint4*)(dl + j * 16) = *(const uint4*)(qkvl + gi + j * 8);
        }
    }
    issueKV(0); CP_COMMIT();
    __syncthreads();

    uint32_t qh[4][4], ql[4][4];
    {
        const uint32_t qa = sb + (uint32_t)(w * 16 + (lane & 15)) * ASTR + (lane >> 4) * 16;
        #pragma unroll
        for (int ks = 0; ks < 4; ++ks) {
            ldsm_x4(qh[ks], qa + ks * 32);
            ldsm_x4(ql[ks], qa + FQ_LO + ks * 32);
        }
    }

    float O[8][4];
    #pragma unroll
    for (int n = 0; n < 8; ++n)
        #pragma unroll
        for (int c = 0; c < 4; ++c) O[n][c] = 0.f;
    float m0 = -1e30f, m1 = -1e30f, l0 = 0.f, l1 = 0.f;

    const uint32_t kRel = (uint32_t)((lane & 7) + ((lane >> 4) & 1) * 8) * ASTR
                        + ((lane >> 3) & 1) * 16;
    const uint32_t vRel = (uint32_t)(lane & 15) * ASTR + (uint32_t)(lane >> 4) * 16;

    const int rowbase = qbase + w * 16;
    const int ktMax = qbase / 64 + 1;
    const float SCL = 0.125f * 1.4426950408889634f;

    for (int kt = 0; kt <= ktMax; ++kt) {
        const int kvbase = kt * 64;
        __syncthreads();
        if (kt + 1 <= ktMax) issueKV(kt + 1);
        CP_COMMIT();
        CP_WAIT1();

        if (kvbase > rowbase + 15) continue;

        const uint32_t stK = sb + FKV0 + (uint32_t)(kt & 1) * KVSTG;
        const uint32_t stV = stK + 18432;

        float S[8][4];
        #pragma unroll
        for (int n = 0; n < 8; ++n)
            #pragma unroll
            for (int c = 0; c < 4; ++c) S[n][c] = 0.f;

        #pragma unroll
        for (int ks = 0; ks < 4; ++ks) {
            uint32_t kb[4][4], kl_[4][4];
            #pragma unroll
            for (int j = 0; j < 4; ++j) {
                const uint32_t ka = stK + kRel + (uint32_t)j * 16 * ASTR + ks * 32;
                ldsm_x4(kb[j],  ka);
                ldsm_x4(kl_[j], ka + 9216);
            }
            #pragma unroll
            for (int n = 0; n < 8; ++n) {
                const int j = n >> 1, hh = (n & 1) * 2;
                mma16816(S[n], qh[ks], kb[j][hh],  kb[j][hh + 1]);
                mma16816(S[n], qh[ks], kl_[j][hh], kl_[j][hh + 1]);
                mma16816(S[n], ql[ks], kb[j][hh],  kb[j][hh + 1]);
            }
        }

        #pragma unroll
        for (int n = 0; n < 8; ++n) {
            S[n][0] *= SCL; S[n][1] *= SCL;
            S[n][2] *= SCL; S[n][3] *= SCL;
        }
        if (kvbase + 63 > rowbase) {
            #pragma unroll
            for (int n = 0; n < 8; ++n) {
                const int colb = kvbase + n * 8 + t2;
                if (colb > rowbase + g)          S[n][0] = -1e30f;
                if (colb + 1 > rowbase + g)      S[n][1] = -1e30f;
                if (colb > rowbase + g + 8)      S[n][2] = -1e30f;
                if (colb + 1 > rowbase + g + 8)  S[n][3] = -1e30f;
            }
        }

        float tm0 = -1e30f, tm1 = -1e30f;
        #pragma unroll
        for (int n = 0; n < 8; ++n) {
            tm0 = fmaxf(tm0, fmaxf(S[n][0], S[n][1]));
            tm1 = fmaxf(tm1, fmaxf(S[n][2], S[n][3]));
        }
        tm0 = fmaxf(tm0, __shfl_xor_sync(0xFFFFFFFFu, tm0, 1));
        tm0 = fmaxf(tm0, __shfl_xor_sync(0xFFFFFFFFu, tm0, 2));
        tm1 = fmaxf(tm1, __shfl_xor_sync(0xFFFFFFFFu, tm1, 1));
        tm1 = fmaxf(tm1, __shfl_xor_sync(0xFFFFFFFFu, tm1, 2));

        const float mn0 = fmaxf(m0, tm0);
        const float mn1 = fmaxf(m1, tm1);
        const float cr0 = exp2f(m0 - mn0);
        const float cr1 = exp2f(m1 - mn1);
        l0 *= cr0; l1 *= cr1;
        #pragma unroll
        for (int n = 0; n < 8; ++n) {
            O[n][0] *= cr0; O[n][1] *= cr0;
            O[n][2] *= cr1; O[n][3] *= cr1;
        }
        #pragma unroll
        for (int n = 0; n < 8; ++n) {
            S[n][0] = exp2f(S[n][0] - mn0);
            S[n][1] = exp2f(S[n][1] - mn0);
            S[n][2] = exp2f(S[n][2] - mn1);
            S[n][3] = exp2f(S[n][3] - mn1);
            l0 += S[n][0] + S[n][1];
            l1 += S[n][2] + S[n][3];
        }
        m0 = mn0; m1 = mn1;

        uint32_t ph[4][4], pl[4][4];
        #pragma unroll
        for (int j = 0; j < 4; ++j) {
            split2(S[2 * j][0],     S[2 * j][1],     ph[j][0], pl[j][0]);
            split2(S[2 * j][2],     S[2 * j][3],     ph[j][1], pl[j][1]);
            split2(S[2 * j + 1][0], S[2 * j + 1][1], ph[j][2], pl[j][2]);
            split2(S[2 * j + 1][2], S[2 * j + 1][3], ph[j][3], pl[j][3]);
        }

        #pragma unroll
        for (int ks = 0; ks < 4; ++ks) {
            uint32_t vb[4][4], vl_[4][4];
            #pragma unroll
            for (int j = 0; j < 4; ++j) {
                const uint32_t va = stV + vRel + (uint32_t)ks * 16 * ASTR + (uint32_t)j * 32;
                ldsm_x4_t(vb[j],  va);
                ldsm_x4_t(vl_[j], va + 9216);
            }
            #pragma unroll
            for (int n = 0; n < 8; ++n) {
                const int j = n >> 1, hh = (n & 1) * 2;
                mma16816(O[n], ph[ks], vb[j][hh],  vb[j][hh + 1]);
                mma16816(O[n], ph[ks], vl_[j][hh], vl_[j][hh + 1]);
                mma16816(O[n], pl[ks], vb[j][hh],  vb[j][hh + 1]);
            }
        }
    }
    CP_WAIT0();

    l0 += __shfl_xor_sync(0xFFFFFFFFu, l0, 1);
    l0 += __shfl_xor_sync(0xFFFFFFFFu, l0, 2);
    l1 += __shfl_xor_sync(0xFFFFFFFFu, l1, 1);
    l1 += __shfl_xor_sync(0xFFFFFFFFu, l1, 2);
    const float inv0 = 1.f / l0;
    const float inv1 = 1.f / l1;

    const size_t row0 = (size_t)(b * SS + rowbase + g);
    #pragma unroll
    for (int n = 0; n < 8; ++n) {
        const int c = h * DEPTH + n * 8 + t2;
        uint32_t hi, lo;
        split2(O[n][0] * inv0, O[n][1] * inv0, hi, lo);
        *(uint32_t*)&outh[row0 * DD + c] = hi;
        *(uint32_t*)&outl[row0 * DD + c] = lo;
        split2(O[n][2] * inv1, O[n][3] * inv1, hi, lo);
        *(uint32_t*)&outh[(row0 + 8) * DD + c] = hi;
        *(uint32_t*)&outl[(row0 + 8) * DD + c] = lo;
    }
}

// ---------------------------------------------------------------------------
// Launch: 1 merged split prep -> QKV GEMM(split out) -> flash attn
//         -> out GEMM(f32 out).
// ---------------------------------------------------------------------------
extern "C" void kernel_launch(void* const* d_in, const int* in_sizes, int n_in,
                              void* d_out, int out_size)
{
    const float* x     = (const float*)d_in[0];
    const float* Wqkv  = (const float*)d_in[2];
    const float* bqkv  = (const float*)d_in[3];
    const float* Wout  = (const float*)d_in[4];
    const float* bout  = (const float*)d_in[5];
    float* out = (float*)d_out;

    __nv_bfloat16 *xh, *xl, *wqh, *wql, *woh, *wol, *qh, *ql, *ah, *al;
    { void* p; cudaGetSymbolAddress(&p, g_xh);  xh  = (__nv_bfloat16*)p; }
    { void* p; cudaGetSymbolAddress(&p, g_xl);  xl  = (__nv_bfloat16*)p; }
    { void* p; cudaGetSymbolAddress(&p, g_wqh); wqh = (__nv_bfloat16*)p; }
    { void* p; cudaGetSymbolAddress(&p, g_wql); wql = (__nv_bfloat16*)p; }
    { void* p; cudaGetSymbolAddress(&p, g_woh); woh = (__nv_bfloat16*)p; }
    { void* p; cudaGetSymbolAddress(&p, g_wol); wol = (__nv_bfloat16*)p; }
    { void* p; cudaGetSymbolAddress(&p, g_qh);  qh  = (__nv_bfloat16*)p; }
    { void* p; cudaGetSymbolAddress(&p, g_ql);  ql  = (__nv_bfloat16*)p; }
    { void* p; cudaGetSymbolAddress(&p, g_ah);  ah  = (__nv_bfloat16*)p; }
    { void* p; cudaGetSymbolAddress(&p, g_al);  al  = (__nv_bfloat16*)p; }

    static bool attr_set = false;
    if (!attr_set) {
        cudaFuncSetAttribute(tgemm_bf16_kernel<true>,
                             cudaFuncAttributeMaxDynamicSharedMemorySize, G_SMEM);
        cudaFuncSetAttribute(tgemm_bf16_kernel<false>,
                             cudaFuncAttributeMaxDynamicSharedMemorySize, G_SMEM);
        cudaFuncSetAttribute(fattn_kernel,
                             cudaFuncAttributeMaxDynamicSharedMemorySize, FATTN_SMEM);
        attr_set = true;
    }

    // 0) merged pre-split of x, W_qkv, W_out (exact multiple: no bounds check)
    split3_kernel<<<(N_X + N_WQ + N_WO) / 4 / 256, 256>>>(
        x, Wqkv, Wout, xh, xl, wqh, wql, woh, wol);

    // 1) QKV projection -> split bf16 qkv
    {
        dim3 grid(QKV_N / 128, MROWS / 64);
        tgemm_bf16_kernel<true><<<grid, 256, G_SMEM>>>(
            xh, xl, wqh, wql, bqkv, qh, ql, QKV_N, DD);
    }
    // 2) causal flash attention -> split bf16 attn (1D LPT grid)
    {
        fattn_kernel<<<NQT * NBH, 256, FATTN_SMEM>>>(qh, ql, ah, al);
    }
    // 3) output projection -> fp32 out
    {
        dim3 grid(DD / 128, MROWS / 64);
        tgemm_bf16_kernel<false><<<grid, 256, G_SMEM>>>(
            ah, al, woh, wol, bout, out, nullptr, DD, DD);
    }
}

// round 17
// speedup vs baseline: 1.0325x; 1.0007x over previous
#include <cuda_runtime.h>
#include <cuda_bf16.h>
#include <cstdint>

// Problem constants
#define BB 2
#define SS 2048
#define DD 1024
#define HH 16
#define DEPTH 64
#define MROWS (BB * SS)          // 4096
#define QKV_N (3 * DD)           // 3072

#define N_X  (MROWS * DD)        // 4194304
#define N_WQ (DD * QKV_N)        // 3145728
#define N_WO (DD * DD)           // 1048576

// Scratch (allocation-free rule: __device__ globals), all bf16 hi/lo pairs
__device__ __nv_bfloat16 g_xh[N_X],  g_xl[N_X];
__device__ __nv_bfloat16 g_wqh[N_WQ], g_wql[N_WQ];
__device__ __nv_bfloat16 g_woh[N_WO], g_wol[N_WO];
__device__ __nv_bfloat16 g_qh[MROWS * QKV_N], g_ql[MROWS * QKV_N];
__device__ __nv_bfloat16 g_ah[N_X], g_al[N_X];

// ===========================================================================
// Helpers (base-target PTX: sm_80+, works on sm_103)
// ===========================================================================
__device__ __forceinline__ uint32_t smem_u32(const void* p) {
    uint32_t a;
    asm("{ .reg .u64 t; cvta.to.shared.u64 t, %1; cvt.u32.u64 %0, t; }"
        : "=r"(a) : "l"(p));
    return a;
}

__device__ __forceinline__ void ldsm_x4(uint32_t* r, uint32_t a) {
    asm volatile("ldmatrix.sync.aligned.m8n8.x4.shared.b16 {%0,%1,%2,%3}, [%4];"
                 : "=r"(r[0]), "=r"(r[1]), "=r"(r[2]), "=r"(r[3]) : "r"(a));
}

__device__ __forceinline__ void ldsm_x4_t(uint32_t* r, uint32_t a) {
    asm volatile("ldmatrix.sync.aligned.m8n8.x4.trans.shared.b16 {%0,%1,%2,%3}, [%4];"
                 : "=r"(r[0]), "=r"(r[1]), "=r"(r[2]), "=r"(r[3]) : "r"(a));
}

__device__ __forceinline__ void mma16816(float* c, const uint32_t* a,
                                         uint32_t b0, uint32_t b1) {
    asm volatile(
        "mma.sync.aligned.m16n8k16.row.col.f32.bf16.bf16.f32 "
        "{%0,%1,%2,%3}, {%4,%5,%6,%7}, {%8,%9}, {%0,%1,%2,%3};"
        : "+f"(c[0]), "+f"(c[1]), "+f"(c[2]), "+f"(c[3])
        : "r"(a[0]), "r"(a[1]), "r"(a[2]), "r"(a[3]), "r"(b0), "r"(b1));
}

__device__ __forceinline__ void cpa16(uint32_t d, const void* s) {
    asm volatile("cp.async.cg.shared.global [%0], [%1], 16;" :: "r"(d), "l"(s));
}
#define CP_COMMIT() asm volatile("cp.async.commit_group;" ::: "memory")
#define CP_WAIT1()  asm volatile("cp.async.wait_group 1;" ::: "memory")
#define CP_WAIT0()  asm volatile("cp.async.wait_group 0;" ::: "memory")

// Split fp32 -> (hi: truncated bf16, lo: rn bf16 of residual). Packs 2 at once.
__device__ __forceinline__ void split2(float x0, float x1,
                                       uint32_t& hi, uint32_t& lo) {
    uint32_t u0 = __float_as_uint(x0), u1 = __float_as_uint(x1);
    uint32_t h0 = u0 & 0xFFFF0000u,    h1 = u1 & 0xFFFF0000u;
    float l0 = x0 - __uint_as_float(h0);
    float l1 = x1 - __uint_as_float(h1);
    hi = (h0 >> 16) | h1;
    __nv_bfloat162 lp = __float22bfloat162_rn(make_float2(l0, l1));
    lo = *reinterpret_cast<uint32_t*>(&lp);
}

// ===========================================================================
// Prep: ONE kernel splitting x, W_qkv, W_out (fp32 -> bf16 hi/lo)
// ===========================================================================
__global__ void split3_kernel(const float* __restrict__ x,
                              const float* __restrict__ wq,
                              const float* __restrict__ wo,
                              __nv_bfloat16* __restrict__ xh, __nv_bfloat16* __restrict__ xl,
                              __nv_bfloat16* __restrict__ wqh, __nv_bfloat16* __restrict__ wql,
                              __nv_bfloat16* __restrict__ woh, __nv_bfloat16* __restrict__ wol)
{
    const int i = (blockIdx.x * blockDim.x + threadIdx.x) * 4;
    const float* src;
    __nv_bfloat16 *oh, *ol;
    int off;
    if (i < N_X)              { src = x;  oh = xh;  ol = xl;  off = i; }
    else if (i < N_X + N_WQ)  { src = wq; oh = wqh; ol = wql; off = i - N_X; }
    else                      { src = wo; oh = woh; ol = wol; off = i - N_X - N_WQ; }

    float4 v = *(const float4*)(src + off);
    uint32_t h0, l0, h1, l1;
    split2(v.x, v.y, h0, l0);
    split2(v.z, v.w, h1, l1);
    *(uint2*)(oh + off) = make_uint2(h0, h1);
    *(uint2*)(ol + off) = make_uint2(l0, l1);
}

// ===========================================================================
// bf16 hi/lo GEMM + bias. BM=64, BN=128, BK=32. 8 warps = 2(m) x 4(n),
// warp tile 32x32. OCC-3, 2-stage ring, SAFE ordering:
//   wait0(own copies of ck) -> sync(publish) -> issue(ck+1) -> compute(ck)
// (loads of ck+1 overlap compute of ck; waited at top of next iteration).
// Stage (27648 B): Ah 0 (64x80) | Al 5120 | Bh 10240 (32x272) | Bl 18944
// ===========================================================================
#define GSTAGE 27648
#define G_SMEM (2 * GSTAGE)

template<bool SPLIT_OUT>
__global__ __launch_bounds__(256, 3) void tgemm_bf16_kernel(
    const __nv_bfloat16* __restrict__ Ah, const __nv_bfloat16* __restrict__ Al,
    const __nv_bfloat16* __restrict__ Bh, const __nv_bfloat16* __restrict__ Bl,
    const float* __restrict__ bias,
    void* __restrict__ Cp, void* __restrict__ Clp,
    int N, int K)
{
    extern __shared__ char sm[];
    const uint32_t sb = smem_u32(sm);

    const int tid  = threadIdx.x;
    const int lane = tid & 31;
    const int wid  = tid >> 5;
    const int wm   = wid & 1;          // 0..1 -> rows wm*32
    const int wn   = wid >> 1;         // 0..3 -> cols wn*32

    const int rowBase = blockIdx.y * 64;
    const int colBase = blockIdx.x * 128;

    // loader mappings
    const int aRow = tid >> 2;             // 0..63
    const int aE0  = (tid & 3) * 8;        // 0,8,16,24 elems
    const int bK   = tid >> 3;             // 0..31
    const int bE0  = (tid & 7) * 16;       // 0..112 elems

    // ldmatrix bases (relative to stage start)
    const int laneM = lane & 15;
    const int laneH = lane >> 4;
    uint32_t aRel[2], bRel[2];
    #pragma unroll
    for (int i = 0; i < 2; ++i)
        aRel[i] = (uint32_t)(wm * 32 + i * 16 + laneM) * 80 + laneH * 16;
    #pragma unroll
    for (int j = 0; j < 2; ++j)
        bRel[j] = 10240u + (uint32_t)laneM * 272
                + (uint32_t)(wn * 32 + j * 16 + laneH * 8) * 2;

    float acc[2][4][4];
    #pragma unroll
    for (int i = 0; i < 2; ++i)
        #pragma unroll
        for (int n = 0; n < 4; ++n)
            #pragma unroll
            for (int c = 0; c < 4; ++c) acc[i][n][c] = 0.f;

    const int nChunks = K >> 5;

    auto issue = [&](int ck) {
        const uint32_t st = sb + (uint32_t)(ck & 1) * GSTAGE;
        const int k0 = ck << 5;
        {   // A rows: 4 threads/row, 8 elems (16B) each
            const size_t gi = (size_t)(rowBase + aRow) * K + k0 + aE0;
            const uint32_t d = st + (uint32_t)aRow * 80 + aE0 * 2;
            cpa16(d,        Ah + gi);
            cpa16(d + 5120, Al + gi);
        }
        {   // B rows [k][n]: 8 threads/row, 16 elems (2x16B) each
            const size_t gi = (size_t)(k0 + bK) * N + colBase + bE0;
            const uint32_t d = st + 10240u + (uint32_t)bK * 272 + bE0 * 2;
            cpa16(d,             Bh + gi);
            cpa16(d + 16,        Bh + gi + 8);
            cpa16(d + 8704,      Bl + gi);
            cpa16(d + 8704 + 16, Bl + gi + 8);
        }
    };

    issue(0); CP_COMMIT();

    for (int ck = 0; ck < nChunks; ++ck) {
        CP_WAIT0();          // own copies of chunk ck landed
        __syncthreads();     // publish all threads' copies; done reading ck-1
        if (ck + 1 < nChunks) issue(ck + 1);   // other buffer, freed at ck-1
        CP_COMMIT();

        const uint32_t st = sb + (uint32_t)(ck & 1) * GSTAGE;
        #pragma unroll
        for (int ks = 0; ks < 2; ++ks) {
            const uint32_t aOff = st + ks * 32;
            const uint32_t bOff = st + ks * 16 * 272;
            uint32_t ah[2][4], al[2][4], bh[2][4], bl[2][4];
            #pragma unroll
            for (int i = 0; i < 2; ++i) {
                ldsm_x4(ah[i], aRel[i] + aOff);
                ldsm_x4(al[i], aRel[i] + aOff + 5120);
            }
            #pragma unroll
            for (int j = 0; j < 2; ++j) {
                ldsm_x4_t(bh[j], bRel[j] + bOff);
                ldsm_x4_t(bl[j], bRel[j] + bOff + 8704);
            }
            #pragma unroll
            for (int i = 0; i < 2; ++i) {
                #pragma unroll
                for (int n = 0; n < 4; ++n) {
                    const int j = n >> 1, h = (n & 1) * 2;
                    mma16816(acc[i][n], ah[i], bh[j][h], bh[j][h + 1]);
                    mma16816(acc[i][n], ah[i], bl[j][h], bl[j][h + 1]);
                    mma16816(acc[i][n], al[i], bh[j][h], bh[j][h + 1]);
                }
            }
        }
    }
    CP_WAIT0();

    // ---- epilogue ----------------------------------------------------------
    #pragma unroll
    for (int i = 0; i < 2; ++i) {
        const int r0 = rowBase + wm * 32 + i * 16 + (lane >> 2);
        #pragma unroll
        for (int n = 0; n < 4; ++n) {
            const int c = colBase + wn * 32 + n * 8 + (lane & 3) * 2;
            const float b0 = bias[c], b1 = bias[c + 1];
            const float v00 = acc[i][n][0] + b0, v01 = acc[i][n][1] + b1;
            const float v10 = acc[i][n][2] + b0, v11 = acc[i][n][3] + b1;
            if (SPLIT_OUT) {
                __nv_bfloat16* Ch = (__nv_bfloat16*)Cp;
                __nv_bfloat16* Cl = (__nv_bfloat16*)Clp;
                uint32_t hi, lo;
                split2(v00, v01, hi, lo);
                *(uint32_t*)&Ch[(size_t)r0 * N + c] = hi;
                *(uint32_t*)&Cl[(size_t)r0 * N + c] = lo;
                split2(v10, v11, hi, lo);
                *(uint32_t*)&Ch[(size_t)(r0 + 8) * N + c] = hi;
                *(uint32_t*)&Cl[(size_t)(r0 + 8) * N + c] = lo;
            } else {
                float* Cc = (float*)Cp;
                *(float2*)&Cc[(size_t)r0 * N + c]       = make_float2(v00, v01);
                *(float2*)&Cc[(size_t)(r0 + 8) * N + c] = make_float2(v10, v11);
            }
        }
    }
}

// ===========================================================================
// Tensor-core causal flash attention (R14/R15 verified version, unchanged).
// 1D grid with GLOBAL LPT order; exp2-domain softmax.
// kv loop: sync -> issue(kt+1) -> wait_group 1 -> compute(kt).
// smem: Q_hi 0, Q_lo 18432; KV stage s at 36864 + s*36864. Total 110592.
// ===========================================================================
#define ASTR 144
#define FQ_LO 18432
#define FKV0 36864
#define KVSTG 36864
#define FATTN_SMEM 110592
#define NQT (SS / 128)        // 16 q tiles
#define NBH (BB * HH)         // 32 heads

__global__ __launch_bounds__(256, 2) void fattn_kernel(
    const __nv_bfloat16* __restrict__ qkvh,
    const __nv_bfloat16* __restrict__ qkvl,
    __nv_bfloat16* __restrict__ outh,
    __nv_bfloat16* __restrict__ outl)
{
    extern __shared__ char sm[];
    const uint32_t sb = smem_u32(sm);

    const int tid  = threadIdx.x;
    const int lane = tid & 31;
    const int w    = tid >> 5;
    const int g    = lane >> 2;
    const int t2   = (lane & 3) * 2;

    const int qt = (NQT - 1) - (int)(blockIdx.x >> 5);
    const int bh = blockIdx.x & (NBH - 1);
    const int b  = bh >> 4;
    const int h  = bh & 15;
    const int qbase = qt * 128;

    const int kvR  = tid >> 2;
    const int kvC0 = (tid & 3) * 16;
    auto issueKV = [&](int kt) {
        const uint32_t st = sb + FKV0 + (uint32_t)(kt & 1) * KVSTG;
        const size_t gi = (size_t)(b * SS + kt * 64 + kvR) * QKV_N + h * 192 + 64 + kvC0;
        const uint32_t d = st + (uint32_t)kvR * ASTR + kvC0 * 2;
        cpa16(d,              qkvh + gi);
        cpa16(d + 16,         qkvh + gi + 8);
        cpa16(d + 9216,       qkvl + gi);
        cpa16(d + 9216 + 16,  qkvl + gi + 8);
        cpa16(d + 18432,      qkvh + gi + 64);
        cpa16(d + 18432 + 16, qkvh + gi + 72);
        cpa16(d + 27648,      qkvl + gi + 64);
        cpa16(d + 27648 + 16, qkvl + gi + 72);
    };

    {
        const int qrow = tid >> 1;
        const int qc0  = (tid & 1) * 32;
        const size_t gi = (size_t)(b * SS + qbase + qrow) * QKV_N + h * 192 + qc0;
        char* dh = sm + qrow * ASTR + qc0 * 2;
        char* dl = sm + FQ_LO + qrow * ASTR + qc0 * 2;
        #pragma unroll
        for (int j = 0; j < 4; ++j) {
            *(uint4*)(dh + j * 16) = *(const uint4*)(qkvh + gi + j * 8);
            *(uint4*)(dl + j * 16) = *(const uint4*)(qkvl + gi + j * 8);
        }
    }
    issueKV(0); CP_COMMIT();
    __syncthreads();

    uint32_t qh[4][4], ql[4][4];
    {
        const uint32_t qa = sb + (uint32_t)(w * 16 + (lane & 15)) * ASTR + (lane >> 4) * 16;
        #pragma unroll
        for (int ks = 0; ks < 4; ++ks) {
            ldsm_x4(qh[ks], qa + ks * 32);
            ldsm_x4(ql[ks], qa + FQ_LO + ks * 32);
        }
    }

    float O[8][4];
    #pragma unroll
    for (int n = 0; n < 8; ++n)
        #pragma unroll
        for (int c = 0; c < 4; ++c) O[n][c] = 0.f;
    float m0 = -1e30f, m1 = -1e30f, l0 = 0.f, l1 = 0.f;

    const uint32_t kRel = (uint32_t)((lane & 7) + ((lane >> 4) & 1) * 8) * ASTR
                        + ((lane >> 3) & 1) * 16;
    const uint32_t vRel = (uint32_t)(lane & 15) * ASTR + (uint32_t)(lane >> 4) * 16;

    const int rowbase = qbase + w * 16;
    const int ktMax = qbase / 64 + 1;
    const float SCL = 0.125f * 1.4426950408889634f;

    for (int kt = 0; kt <= ktMax; ++kt) {
        const int kvbase = kt * 64;
        __syncthreads();
        if (kt + 1 <= ktMax) issueKV(kt + 1);
        CP_COMMIT();
        CP_WAIT1();

        if (kvbase > rowbase + 15) continue;

        const uint32_t stK = sb + FKV0 + (uint32_t)(kt & 1) * KVSTG;
        const uint32_t stV = stK + 18432;

        float S[8][4];
        #pragma unroll
        for (int n = 0; n < 8; ++n)
            #pragma unroll
            for (int c = 0; c < 4; ++c) S[n][c] = 0.f;

        #pragma unroll
        for (int ks = 0; ks < 4; ++ks) {
            uint32_t kb[4][4], kl_[4][4];
            #pragma unroll
            for (int j = 0; j < 4; ++j) {
                const uint32_t ka = stK + kRel + (uint32_t)j * 16 * ASTR + ks * 32;
                ldsm_x4(kb[j],  ka);
                ldsm_x4(kl_[j], ka + 9216);
            }
            #pragma unroll
            for (int n = 0; n < 8; ++n) {
                const int j = n >> 1, hh = (n & 1) * 2;
                mma16816(S[n], qh[ks], kb[j][hh],  kb[j][hh + 1]);
                mma16816(S[n], qh[ks], kl_[j][hh], kl_[j][hh + 1]);
                mma16816(S[n], ql[ks], kb[j][hh],  kb[j][hh + 1]);
            }
        }

        #pragma unroll
        for (int n = 0; n < 8; ++n) {
            S[n][0] *= SCL; S[n][1] *= SCL;
            S[n][2] *= SCL; S[n][3] *= SCL;
        }
        if (kvbase + 63 > rowbase) {
            #pragma unroll
            for (int n = 0; n < 8; ++n) {
                const int colb = kvbase + n * 8 + t2;
                if (colb > rowbase + g)          S[n][0] = -1e30f;
                if (colb + 1 > rowbase + g)      S[n][1] = -1e30f;
                if (colb > rowbase + g + 8)      S[n][2] = -1e30f;
                if (colb + 1 > rowbase + g + 8)  S[n][3] = -1e30f;
            }
        }

        float tm0 = -1e30f, tm1 = -1e30f;
        #pragma unroll
        for (int n = 0; n < 8; ++n) {
            tm0 = fmaxf(tm0, fmaxf(S[n][0], S[n][1]));
            tm1 = fmaxf(tm1, fmaxf(S[n][2], S[n][3]));
        }
        tm0 = fmaxf(tm0, __shfl_xor_sync(0xFFFFFFFFu, tm0, 1));
        tm0 = fmaxf(tm0, __shfl_xor_sync(0xFFFFFFFFu, tm0, 2));
        tm1 = fmaxf(tm1, __shfl_xor_sync(0xFFFFFFFFu, tm1, 1));
        tm1 = fmaxf(tm1, __shfl_xor_sync(0xFFFFFFFFu, tm1, 2));

        const float mn0 = fmaxf(m0, tm0);
        const float mn1 = fmaxf(m1, tm1);
        const float cr0 = exp2f(m0 - mn0);
        const float cr1 = exp2f(m1 - mn1);
        l0 *= cr0; l1 *= cr1;
        #pragma unroll
        for (int n = 0; n < 8; ++n) {
            O[n][0] *= cr0; O[n][1] *= cr0;
            O[n][2] *= cr1; O[n][3] *= cr1;
        }
        #pragma unroll
        for (int n = 0; n < 8; ++n) {
            S[n][0] = exp2f(S[n][0] - mn0);
            S[n][1] = exp2f(S[n][1] - mn0);
            S[n][2] = exp2f(S[n][2] - mn1);
            S[n][3] = exp2f(S[n][3] - mn1);
            l0 += S[n][0] + S[n][1];
            l1 += S[n][2] + S[n][3];
        }
        m0 = mn0; m1 = mn1;

        uint32_t ph[4][4], pl[4][4];
        #pragma unroll
        for (int j = 0; j < 4; ++j) {
            split2(S[2 * j][0],     S[2 * j][1],     ph[j][0], pl[j][0]);
            split2(S[2 * j][2],     S[2 * j][3],     ph[j][1], pl[j][1]);
            split2(S[2 * j + 1][0], S[2 * j + 1][1], ph[j][2], pl[j][2]);
            split2(S[2 * j + 1][2], S[2 * j + 1][3], ph[j][3], pl[j][3]);
        }

        #pragma unroll
        for (int ks = 0; ks < 4; ++ks) {
            uint32_t vb[4][4], vl_[4][4];
            #pragma unroll
            for (int j = 0; j < 4; ++j) {
                const uint32_t va = stV + vRel + (uint32_t)ks * 16 * ASTR + (uint32_t)j * 32;
                ldsm_x4_t(vb[j],  va);
                ldsm_x4_t(vl_[j], va + 9216);
            }
            #pragma unroll
            for (int n = 0; n < 8; ++n) {
                const int j = n >> 1, hh = (n & 1) * 2;
                mma16816(O[n], ph[ks], vb[j][hh],  vb[j][hh + 1]);
                mma16816(O[n], ph[ks], vl_[j][hh], vl_[j][hh + 1]);
                mma16816(O[n], pl[ks], vb[j][hh],  vb[j][hh + 1]);
            }
        }
    }
    CP_WAIT0();

    l0 += __shfl_xor_sync(0xFFFFFFFFu, l0, 1);
    l0 += __shfl_xor_sync(0xFFFFFFFFu, l0, 2);
    l1 += __shfl_xor_sync(0xFFFFFFFFu, l1, 1);
    l1 += __shfl_xor_sync(0xFFFFFFFFu, l1, 2);
    const float inv0 = 1.f / l0;
    const float inv1 = 1.f / l1;

    const size_t row0 = (size_t)(b * SS + rowbase + g);
    #pragma unroll
    for (int n = 0; n < 8; ++n) {
        const int c = h * DEPTH + n * 8 + t2;
        uint32_t hi, lo;
        split2(O[n][0] * inv0, O[n][1] * inv0, hi, lo);
        *(uint32_t*)&outh[row0 * DD + c] = hi;
        *(uint32_t*)&outl[row0 * DD + c] = lo;
        split2(O[n][2] * inv1, O[n][3] * inv1, hi, lo);
        *(uint32_t*)&outh[(row0 + 8) * DD + c] = hi;
        *(uint32_t*)&outl[(row0 + 8) * DD + c] = lo;
    }
}

// ---------------------------------------------------------------------------
// Launch: 1 merged split prep -> QKV GEMM(split out) -> flash attn
//         -> out GEMM(f32 out).
// ---------------------------------------------------------------------------
extern "C" void kernel_launch(void* const* d_in, const int* in_sizes, int n_in,
                              void* d_out, int out_size)
{
    const float* x     = (const float*)d_in[0];
    const float* Wqkv  = (const float*)d_in[2];
    const float* bqkv  = (const float*)d_in[3];
    const float* Wout  = (const float*)d_in[4];
    const float* bout  = (const float*)d_in[5];
    float* out = (float*)d_out;

    __nv_bfloat16 *xh, *xl, *wqh, *wql, *woh, *wol, *qh, *ql, *ah, *al;
    { void* p; cudaGetSymbolAddress(&p, g_xh);  xh  = (__nv_bfloat16*)p; }
    { void* p; cudaGetSymbolAddress(&p, g_xl);  xl  = (__nv_bfloat16*)p; }
    { void* p; cudaGetSymbolAddress(&p, g_wqh); wqh = (__nv_bfloat16*)p; }
    { void* p; cudaGetSymbolAddress(&p, g_wql); wql = (__nv_bfloat16*)p; }
    { void* p; cudaGetSymbolAddress(&p, g_woh); woh = (__nv_bfloat16*)p; }
    { void* p; cudaGetSymbolAddress(&p, g_wol); wol = (__nv_bfloat16*)p; }
    { void* p; cudaGetSymbolAddress(&p, g_qh);  qh  = (__nv_bfloat16*)p; }
    { void* p; cudaGetSymbolAddress(&p, g_ql);  ql  = (__nv_bfloat16*)p; }
    { void* p; cudaGetSymbolAddress(&p, g_ah);  ah  = (__nv_bfloat16*)p; }
    { void* p; cudaGetSymbolAddress(&p, g_al);  al  = (__nv_bfloat16*)p; }

    static bool attr_set = false;
    if (!attr_set) {
        cudaFuncSetAttribute(tgemm_bf16_kernel<true>,
                             cudaFuncAttributeMaxDynamicSharedMemorySize, G_SMEM);
        cudaFuncSetAttribute(tgemm_bf16_kernel<false>,
                             cudaFuncAttributeMaxDynamicSharedMemorySize, G_SMEM);
        cudaFuncSetAttribute(fattn_kernel,
                             cudaFuncAttributeMaxDynamicSharedMemorySize, FATTN_SMEM);
        attr_set = true;
    }

    // 0) merged pre-split of x, W_qkv, W_out (exact multiple: no bounds check)
    split3_kernel<<<(N_X + N_WQ + N_WO) / 4 / 256, 256>>>(
        x, Wqkv, Wout, xh, xl, wqh, wql, woh, wol);

    // 1) QKV projection -> split bf16 qkv
    {
        dim3 grid(QKV_N / 128, MROWS / 64);
        tgemm_bf16_kernel<true><<<grid, 256, G_SMEM>>>(
            xh, xl, wqh, wql, bqkv, qh, ql, QKV_N, DD);
    }
    // 2) causal flash attention -> split bf16 attn (1D LPT grid)
    {
        fattn_kernel<<<NQT * NBH, 256, FATTN_SMEM>>>(qh, ql, ah, al);
    }
    // 3) output projection -> fp32 out
    {
        dim3 grid(DD / 128, MROWS / 64);
        tgemm_bf16_kernel<false><<<grid, 256, G_SMEM>>>(
            ah, al, woh, wol, bout, out, nullptr, DD, DD);
    }
}